// round 1
// baseline (speedup 1.0000x reference)
#include <cuda_runtime.h>

// Problem constants
#define NB   64
#define NN   256
#define NH   8
#define NDH  64
#define ND   512
#define NTOT 16384      // B*N
#define NE   262144     // TOTAL*DEG
#define NG   512        // H*B graphs

// ---------------- device scratch (no allocations allowed) ----------------
__device__ int            g_is64;
__device__ float          g_coeff[NG * 4];
__device__ float          g_dinv[NTOT];
__device__ int            g_deg[NTOT];
__device__ int            g_off[NTOT + 1];
__device__ int            g_cur[NTOT];
__device__ unsigned short g_esrc[NE];
__device__ float          g_enorm[NE];
__device__ float          g_filt[(size_t)NTOT * ND];   // 33.5 MB, row = n*64+b (out-row order)

// ---------------- edge dtype detection ----------------
// If edge_index is int64, every odd 32-bit word (the high half, values < 16384)
// is zero. If int32, odd words are random node ids -> ~never all zero.
__global__ void k_detect(const int* p) {
    if (blockIdx.x == 0 && threadIdx.x == 0) {
        int ok64 = 1;
        for (int q = 1; q < 64; q += 2)
            if (p[q] != 0) ok64 = 0;
        g_is64 = ok64;
    }
}

__device__ __forceinline__ void load_edge(const void* ei, int e, int& s, int& d) {
    if (g_is64) {
        const long long* p = (const long long*)ei;
        s = (int)p[e];
        d = (int)p[NE + e];
    } else {
        const int* p = (const int*)ei;
        s = p[e];
        d = p[NE + e];
    }
}

// ---------------- stage 1: GCN coeff per graph ----------------
// One block per graph g = h*B + b. Two passes over attn[b,h] (256x256).
__global__ void __launch_bounds__(256) k_coeff(const float* __restrict__ attn,
                                               const float* __restrict__ Wg,
                                               const float* __restrict__ bg,
                                               const float* __restrict__ Wl,
                                               const float* __restrict__ bl) {
    int g = blockIdx.x;
    int h = g >> 6;          // g = h*64 + b
    int b = g & 63;
    const float* A = attn + ((size_t)b * NH + h) * (NN * NN);
    int j = threadIdx.x;

    __shared__ float dsm[NN];
    __shared__ float red[4];

    // pass 1: column sums -> deg = colsum + 1 (diagonal of A_hat)
    float cs = 0.f;
#pragma unroll 8
    for (int i = 0; i < NN; i++) cs += A[i * NN + j];
    float deg = cs + 1.0f;
    float dv = (deg > 0.f) ? rsqrtf(deg) : 0.f;
    dsm[j] = dv;
    if (j < 4) red[j] = 0.f;
    __syncthreads();

    // pass 2: s[j] = (sum_i dinv[i]*A[i,j] + dinv[j]) * dinv[j]
    float t = 0.f;
#pragma unroll 8
    for (int i = 0; i < NN; i++) t += dsm[i] * A[i * NN + j];
    float sj = (t + dv) * dv;

    float w_row[4], v[4];
#pragma unroll
    for (int c = 0; c < 4; c++)
        w_row[c] = Wg[c] + Wg[4 + c] + Wg[8 + c] + Wg[12 + c];
#pragma unroll
    for (int c = 0; c < 4; c++)
        v[c] = tanhf(sj * w_row[c] + bg[c]);

    // block reduce 4 values
#pragma unroll
    for (int c = 0; c < 4; c++) {
#pragma unroll
        for (int off = 16; off > 0; off >>= 1)
            v[c] += __shfl_xor_sync(0xffffffffu, v[c], off);
    }
    if ((j & 31) == 0) {
#pragma unroll
        for (int c = 0; c < 4; c++) atomicAdd(&red[c], v[c]);
    }
    __syncthreads();

    if (j == 0) {
        float gap[4];
#pragma unroll
        for (int c = 0; c < 4; c++) gap[c] = red[c] * (1.0f / 256.0f);
#pragma unroll
        for (int c2 = 0; c2 < 4; c2++) {
            float cc = bl[c2];
#pragma unroll
            for (int c = 0; c < 4; c++) cc += gap[c] * Wl[c * 4 + c2];
            g_coeff[g * 4 + c2] = cc;
        }
    }
}

// ---------------- stage 2: edge CSR build ----------------
__global__ void k_zero() {
    int i = blockIdx.x * blockDim.x + threadIdx.x;
    if (i < NTOT) { g_deg[i] = 0; g_cur[i] = 0; }
}

__global__ void k_degk(const void* ei) {
    int e = blockIdx.x * blockDim.x + threadIdx.x;
    if (e < NE) {
        int s, d;
        load_edge(ei, e, s, d);
        atomicAdd(&g_deg[d], 1);
    }
}

// single block, 512 threads, 32 nodes each: dinv_n + exclusive-scan offsets
__global__ void __launch_bounds__(512) k_scan() {
    __shared__ int sc[512];
    int t = threadIdx.x;
    int base = t * 32;
    int sum = 0;
    for (int i = 0; i < 32; i++) {
        int d = g_deg[base + i];
        g_dinv[base + i] = (d > 0) ? rsqrtf((float)d) : 0.f;
        sum += d;
    }
    sc[t] = sum;
    __syncthreads();
    for (int off = 1; off < 512; off <<= 1) {
        int v = sc[t];
        int u = (t >= off) ? sc[t - off] : 0;
        __syncthreads();
        sc[t] = v + u;
        __syncthreads();
    }
    int run = sc[t] - sum;   // exclusive base
    for (int i = 0; i < 32; i++) {
        g_off[base + i] = run;
        run += g_deg[base + i];
    }
    if (t == 511) g_off[NTOT] = sc[511];
}

__global__ void k_scatter(const void* ei) {
    int e = blockIdx.x * blockDim.x + threadIdx.x;
    if (e < NE) {
        int s, d;
        load_edge(ei, e, s, d);
        float nm = -(g_dinv[s] * g_dinv[d]);
        int pos = g_off[d] + atomicAdd(&g_cur[d], 1);
        g_esrc[pos]  = (unsigned short)(s & (NN - 1));  // same-graph edges: local id
        g_enorm[pos] = nm;
    }
}

// ---------------- stage 3: Chebyshev propagation + per-head matmul ----------------
// One block per graph (h,b). 512 threads = 16 warps; warp w owns nodes {w, w+16, ...}
// (16 nodes), lane owns features (lane, lane+32). All T_k buffers live in smem.
__global__ void __launch_bounds__(512, 1) k_cheb(const float* __restrict__ oeh,
                                                 const float* __restrict__ Wch,
                                                 const float* __restrict__ bch) {
    extern __shared__ float sm[];
    float* S0 = sm;
    float* S1 = sm + NN * NDH;
    float* S2 = sm + 2 * NN * NDH;

    int g = blockIdx.x;
    int h = g >> 6;
    int b = g & 63;
    int tid = threadIdx.x;
    int w = tid >> 5;
    int lane = tid & 31;

    // load x0: oeh[((b*256+n)*8+h)*64+d]
    const float* xb = oeh + (size_t)b * 131072 + (size_t)h * 64;
    for (int idx = tid; idx < NN * NDH; idx += 512) {
        int n = idx >> 6, d = idx & 63;
        S0[idx] = xb[(size_t)n * 512 + d];
    }

    float c[4];
#pragma unroll
    for (int k = 0; k < 4; k++) c[k] = g_coeff[g * 4 + k];

    float acc0[16], acc1[16];
#pragma unroll
    for (int i = 0; i < 16; i++) { acc0[i] = 0.f; acc1[i] = 0.f; }

    __syncthreads();

    auto matmul = [&](const float* T, int k, float ck) {
        const float* Wk = Wch + k * 4096;
        for (int jc = 0; jc < 64; jc += 16) {
            float W0[16], W1[16];
#pragma unroll
            for (int jj = 0; jj < 16; jj++) {
                W0[jj] = ck * Wk[(jc + jj) * 64 + lane];
                W1[jj] = ck * Wk[(jc + jj) * 64 + lane + 32];
            }
#pragma unroll 4
            for (int jj = 0; jj < 16; jj++) {
                int j = jc + jj;
#pragma unroll
                for (int i = 0; i < 16; i++) {
                    float tv = T[(i * 16 + w) * 64 + j];   // broadcast LDS
                    acc0[i] += tv * W0[jj];
                    acc1[i] += tv * W1[jj];
                }
            }
        }
    };

    auto prop = [&](const float* Tsrc, const float* Tprev, float* Tdst, bool first) {
        for (int i = 0; i < 16; i++) {
            int n = i * 16 + w;
            int dn = b * NN + n;
            int eb = g_off[dn], ee = g_off[dn + 1];
            float s0 = 0.f, s1 = 0.f;
            for (int e0 = eb; e0 < ee; e0 += 32) {
                int me = e0 + lane;
                int sl = 0; float wn = 0.f;
                if (me < ee) { sl = g_esrc[me]; wn = g_enorm[me]; }
                int cnt = min(32, ee - e0);
                for (int q = 0; q < cnt; q++) {
                    int ss  = __shfl_sync(0xffffffffu, sl, q);
                    float ww = __shfl_sync(0xffffffffu, wn, q);
                    s0 += ww * Tsrc[ss * 64 + lane];
                    s1 += ww * Tsrc[ss * 64 + lane + 32];
                }
            }
            int o = n * 64 + lane;
            if (first) { Tdst[o] = s0; Tdst[o + 32] = s1; }
            else {
                Tdst[o]      = 2.f * s0 - Tprev[o];
                Tdst[o + 32] = 2.f * s1 - Tprev[o + 32];
            }
        }
    };

    matmul(S0, 0, c[0]);            // k=0 : T0 = x0
    prop(S0, nullptr, S1, true);    // T1 = prop(T0)   (S0 fully written before last sync)
    matmul(S1, 1, c[1]);            // own rows only
    __syncthreads();
    prop(S1, S0, S2, false);        // T2 = 2*prop(T1) - T0
    matmul(S2, 2, c[2]);
    __syncthreads();
    prop(S2, S1, S0, false);        // T3 = 2*prop(T2) - T1  (S0 rows reusable)
    matmul(S0, 3, c[3]);

    float bc0 = bch[lane], bc1 = bch[lane + 32];
    for (int i = 0; i < 16; i++) {
        int n = i * 16 + w;
        size_t base = ((size_t)(n * 64 + b)) * ND + h * 64;   // out-row order
        g_filt[base + lane]      = acc0[i] + bc0;
        g_filt[base + lane + 32] = acc1[i] + bc1;
    }
}

// ---------------- stage 4: fused concat-GEMM + LayerNorm ----------------
// Block: 32 rows x 512 cols, 256 threads (tx 0..63 cols*8, ty 0..3 rows*8).
__global__ void __launch_bounds__(256) k_final(const float* __restrict__ outp,
                                               const float* __restrict__ Wc,
                                               const float* __restrict__ bc,
                                               const float* __restrict__ gamma,
                                               const float* __restrict__ beta,
                                               float* __restrict__ out) {
    __shared__ float Bs[16 * 512];
    __shared__ float As[16 * 33];
    __shared__ float redS[4][8][2];
    __shared__ float redQ[4][8][2];

    int tid = threadIdx.x;
    int tx = tid & 63;
    int ty = tid >> 6;
    int r0 = blockIdx.x * 32;

    float acc[8][8];
#pragma unroll
    for (int i = 0; i < 8; i++)
#pragma unroll
        for (int j = 0; j < 8; j++) acc[i][j] = 0.f;

    for (int kb = 0; kb < 1024; kb += 16) {
        const float* Asrc = (kb < 512) ? outp : g_filt;
        int ko = (kb < 512) ? kb : (kb - 512);

        // A tile 32x16 -> As[k][r] (transposed)
        int l = tid * 2;
#pragma unroll
        for (int q = 0; q < 2; q++) {
            int li = l + q;
            int r = li >> 4, kk = li & 15;
            As[kk * 33 + r] = Asrc[(size_t)(r0 + r) * ND + ko + kk];
        }
        // B tile 16x512: contiguous rows of W_cat
        const float4* Wv = (const float4*)(Wc + (size_t)kb * ND);
        float4* Bv = (float4*)Bs;
#pragma unroll
        for (int q = 0; q < 8; q++) {
            int t4 = tid + q * 256;
            Bv[t4] = Wv[t4];
        }
        __syncthreads();

#pragma unroll
        for (int kk = 0; kk < 16; kk++) {
            float a[8], bb[8];
#pragma unroll
            for (int i = 0; i < 8; i++) a[i] = As[kk * 33 + ty * 8 + i];
            const float4* bp = (const float4*)&Bs[kk * 512 + tx * 8];
            float4 b0 = bp[0], b1 = bp[1];
            bb[0] = b0.x; bb[1] = b0.y; bb[2] = b0.z; bb[3] = b0.w;
            bb[4] = b1.x; bb[5] = b1.y; bb[6] = b1.z; bb[7] = b1.w;
#pragma unroll
            for (int i = 0; i < 8; i++)
#pragma unroll
                for (int j = 0; j < 8; j++) acc[i][j] += a[i] * bb[j];
        }
        __syncthreads();
    }

    // epilogue: + b_cat, LayerNorm over the 512-wide row, * gamma + beta
    float bcv[8], gmv[8], btv[8];
#pragma unroll
    for (int j = 0; j < 8; j++) {
        bcv[j] = bc[tx * 8 + j];
        gmv[j] = gamma[tx * 8 + j];
        btv[j] = beta[tx * 8 + j];
    }
#pragma unroll
    for (int i = 0; i < 8; i++)
#pragma unroll
        for (int j = 0; j < 8; j++) acc[i][j] += bcv[j];

    int half = tx >> 5;
#pragma unroll
    for (int i = 0; i < 8; i++) {
        float ps = 0.f, pq = 0.f;
#pragma unroll
        for (int j = 0; j < 8; j++) { ps += acc[i][j]; pq += acc[i][j] * acc[i][j]; }
#pragma unroll
        for (int off = 16; off > 0; off >>= 1) {
            ps += __shfl_xor_sync(0xffffffffu, ps, off);
            pq += __shfl_xor_sync(0xffffffffu, pq, off);
        }
        if ((tid & 31) == 0) { redS[ty][i][half] = ps; redQ[ty][i][half] = pq; }
    }
    __syncthreads();

#pragma unroll
    for (int i = 0; i < 8; i++) {
        float S = redS[ty][i][0] + redS[ty][i][1];
        float Q = redQ[ty][i][0] + redQ[ty][i][1];
        float mu = S * (1.0f / 512.0f);
        float var = Q * (1.0f / 512.0f) - mu * mu;
        float rstd = rsqrtf(var + 1e-5f);
        float res[8];
#pragma unroll
        for (int j = 0; j < 8; j++)
            res[j] = (acc[i][j] - mu) * rstd * gmv[j] + btv[j];
        float4* dst = (float4*)(out + (size_t)(r0 + ty * 8 + i) * ND + tx * 8);
        dst[0] = make_float4(res[0], res[1], res[2], res[3]);
        dst[1] = make_float4(res[4], res[5], res[6], res[7]);
    }
}

// ---------------- launch ----------------
extern "C" void kernel_launch(void* const* d_in, const int* in_sizes, int n_in,
                              void* d_out, int out_size) {
    const float* outp  = (const float*)d_in[0];   // (N,B,D)
    const float* attn  = (const float*)d_in[1];   // (B,H,N,N)
    const float* oeh   = (const float*)d_in[2];   // (B,N,H,DH)
    const void*  ei    = d_in[3];                 // (2,E) int32 or int64 (detected)
    // d_in[4] feature_indices, d_in[5] batch: identity layouts, unused
    const float* Wg    = (const float*)d_in[6];
    const float* bg    = (const float*)d_in[7];
    const float* Wl    = (const float*)d_in[8];
    const float* bl    = (const float*)d_in[9];
    const float* Wch   = (const float*)d_in[10];
    const float* bch   = (const float*)d_in[11];
    const float* Wc    = (const float*)d_in[12];
    const float* bc    = (const float*)d_in[13];
    const float* gamma = (const float*)d_in[14];
    const float* beta  = (const float*)d_in[15];
    float* out = (float*)d_out;

    cudaFuncSetAttribute(k_cheb, cudaFuncAttributeMaxDynamicSharedMemorySize, 3 * NN * NDH * 4);

    k_detect<<<1, 32>>>((const int*)ei);
    k_coeff<<<NG, 256>>>(attn, Wg, bg, Wl, bl);
    k_zero<<<NTOT / 256, 256>>>();
    k_degk<<<NE / 256, 256>>>(ei);
    k_scan<<<1, 512>>>();
    k_scatter<<<NE / 256, 256>>>(ei);
    k_cheb<<<NG, 512, 3 * NN * NDH * 4>>>(oeh, Wch, bch);
    k_final<<<NTOT / 32, 256>>>(outp, Wc, bc, gamma, beta, out);
}

// round 2
// speedup vs baseline: 1.1866x; 1.1866x over previous
#include <cuda_runtime.h>

// Problem constants
#define NB   64
#define NN   256
#define NH   8
#define NDH  64
#define ND   512
#define NTOT 16384      // B*N
#define NE   262144     // TOTAL*DEG
#define NG   512        // H*B graphs

// ---------------- device scratch (no allocations allowed) ----------------
__device__ int            g_is64;
__device__ float          g_coeff[NG * 4];
__device__ float          g_dinv[NTOT];
__device__ int            g_deg[NTOT];
__device__ int            g_off[NTOT + 1];
__device__ int            g_cur[NTOT];
__device__ unsigned short g_esrc[NE];
__device__ float          g_enorm[NE];
__device__ float          g_filt[(size_t)NTOT * ND];   // 33.5 MB, row = n*64+b (out-row order)

// ---------------- edge dtype detection ----------------
__global__ void k_detect(const int* p) {
    if (blockIdx.x == 0 && threadIdx.x == 0) {
        int ok64 = 1;
        for (int q = 1; q < 64; q += 2)
            if (p[q] != 0) ok64 = 0;
        g_is64 = ok64;
    }
}

__device__ __forceinline__ void load_edge(const void* ei, int e, int& s, int& d) {
    if (g_is64) {
        const long long* p = (const long long*)ei;
        s = (int)p[e];
        d = (int)p[NE + e];
    } else {
        const int* p = (const int*)ei;
        s = p[e];
        d = p[NE + e];
    }
}

// ---------------- stage 1: GCN coeff per graph ----------------
__global__ void __launch_bounds__(256) k_coeff(const float* __restrict__ attn,
                                               const float* __restrict__ Wg,
                                               const float* __restrict__ bg,
                                               const float* __restrict__ Wl,
                                               const float* __restrict__ bl) {
    int g = blockIdx.x;
    int h = g >> 6;
    int b = g & 63;
    const float* A = attn + ((size_t)b * NH + h) * (NN * NN);
    int j = threadIdx.x;

    __shared__ float dsm[NN];
    __shared__ float red[4];

    float cs = 0.f;
#pragma unroll 8
    for (int i = 0; i < NN; i++) cs += A[i * NN + j];
    float deg = cs + 1.0f;
    float dv = (deg > 0.f) ? rsqrtf(deg) : 0.f;
    dsm[j] = dv;
    if (j < 4) red[j] = 0.f;
    __syncthreads();

    float t = 0.f;
#pragma unroll 8
    for (int i = 0; i < NN; i++) t += dsm[i] * A[i * NN + j];
    float sj = (t + dv) * dv;

    float w_row[4], v[4];
#pragma unroll
    for (int c = 0; c < 4; c++)
        w_row[c] = Wg[c] + Wg[4 + c] + Wg[8 + c] + Wg[12 + c];
#pragma unroll
    for (int c = 0; c < 4; c++)
        v[c] = tanhf(sj * w_row[c] + bg[c]);

#pragma unroll
    for (int c = 0; c < 4; c++) {
#pragma unroll
        for (int off = 16; off > 0; off >>= 1)
            v[c] += __shfl_xor_sync(0xffffffffu, v[c], off);
    }
    if ((j & 31) == 0) {
#pragma unroll
        for (int c = 0; c < 4; c++) atomicAdd(&red[c], v[c]);
    }
    __syncthreads();

    if (j == 0) {
        float gap[4];
#pragma unroll
        for (int c = 0; c < 4; c++) gap[c] = red[c] * (1.0f / 256.0f);
#pragma unroll
        for (int c2 = 0; c2 < 4; c2++) {
            float cc = bl[c2];
#pragma unroll
            for (int c = 0; c < 4; c++) cc += gap[c] * Wl[c * 4 + c2];
            g_coeff[g * 4 + c2] = cc;
        }
    }
}

// ---------------- stage 2: edge CSR build ----------------
__global__ void k_zero() {
    int i = blockIdx.x * blockDim.x + threadIdx.x;
    if (i < NTOT) { g_deg[i] = 0; g_cur[i] = 0; }
}

__global__ void k_degk(const void* ei) {
    int e = blockIdx.x * blockDim.x + threadIdx.x;
    if (e < NE) {
        int s, d;
        load_edge(ei, e, s, d);
        atomicAdd(&g_deg[d], 1);
    }
}

__global__ void __launch_bounds__(512) k_scan() {
    __shared__ int sc[512];
    int t = threadIdx.x;
    int base = t * 32;
    int sum = 0;
    for (int i = 0; i < 32; i++) {
        int d = g_deg[base + i];
        g_dinv[base + i] = (d > 0) ? rsqrtf((float)d) : 0.f;
        sum += d;
    }
    sc[t] = sum;
    __syncthreads();
    for (int off = 1; off < 512; off <<= 1) {
        int v = sc[t];
        int u = (t >= off) ? sc[t - off] : 0;
        __syncthreads();
        sc[t] = v + u;
        __syncthreads();
    }
    int run = sc[t] - sum;
    for (int i = 0; i < 32; i++) {
        g_off[base + i] = run;
        run += g_deg[base + i];
    }
    if (t == 511) g_off[NTOT] = sc[511];
}

__global__ void k_scatter(const void* ei) {
    int e = blockIdx.x * blockDim.x + threadIdx.x;
    if (e < NE) {
        int s, d;
        load_edge(ei, e, s, d);
        float nm = -(g_dinv[s] * g_dinv[d]);
        int pos = g_off[d] + atomicAdd(&g_cur[d], 1);
        g_esrc[pos]  = (unsigned short)(s & (NN - 1));
        g_enorm[pos] = nm;
    }
}

// ---------------- stage 3: Chebyshev propagation + per-head matmul ----------------
__global__ void __launch_bounds__(512, 1) k_cheb(const float* __restrict__ oeh,
                                                 const float* __restrict__ Wch,
                                                 const float* __restrict__ bch) {
    extern __shared__ float sm[];
    float* S0 = sm;
    float* S1 = sm + NN * NDH;
    float* S2 = sm + 2 * NN * NDH;

    int g = blockIdx.x;
    int h = g >> 6;
    int b = g & 63;
    int tid = threadIdx.x;
    int w = tid >> 5;
    int lane = tid & 31;

    const float* xb = oeh + (size_t)b * 131072 + (size_t)h * 64;
    for (int idx = tid; idx < NN * NDH; idx += 512) {
        int n = idx >> 6, d = idx & 63;
        S0[idx] = xb[(size_t)n * 512 + d];
    }

    float c[4];
#pragma unroll
    for (int k = 0; k < 4; k++) c[k] = g_coeff[g * 4 + k];

    float acc0[16], acc1[16];
#pragma unroll
    for (int i = 0; i < 16; i++) { acc0[i] = 0.f; acc1[i] = 0.f; }

    __syncthreads();

    auto matmul = [&](const float* T, int k, float ck) {
        const float* Wk = Wch + k * 4096;
        for (int jc = 0; jc < 64; jc += 16) {
            float W0[16], W1[16];
#pragma unroll
            for (int jj = 0; jj < 16; jj++) {
                W0[jj] = ck * Wk[(jc + jj) * 64 + lane];
                W1[jj] = ck * Wk[(jc + jj) * 64 + lane + 32];
            }
#pragma unroll 4
            for (int jj = 0; jj < 16; jj++) {
                int j = jc + jj;
#pragma unroll
                for (int i = 0; i < 16; i++) {
                    float tv = T[(i * 16 + w) * 64 + j];
                    acc0[i] += tv * W0[jj];
                    acc1[i] += tv * W1[jj];
                }
            }
        }
    };

    auto prop = [&](const float* Tsrc, const float* Tprev, float* Tdst, bool first) {
        for (int i = 0; i < 16; i++) {
            int n = i * 16 + w;
            int dn = b * NN + n;
            int eb = g_off[dn], ee = g_off[dn + 1];
            float s0 = 0.f, s1 = 0.f;
            for (int e0 = eb; e0 < ee; e0 += 32) {
                int me = e0 + lane;
                int sl = 0; float wn = 0.f;
                if (me < ee) { sl = g_esrc[me]; wn = g_enorm[me]; }
                int cnt = min(32, ee - e0);
                for (int q = 0; q < cnt; q++) {
                    int ss  = __shfl_sync(0xffffffffu, sl, q);
                    float ww = __shfl_sync(0xffffffffu, wn, q);
                    s0 += ww * Tsrc[ss * 64 + lane];
                    s1 += ww * Tsrc[ss * 64 + lane + 32];
                }
            }
            int o = n * 64 + lane;
            if (first) { Tdst[o] = s0; Tdst[o + 32] = s1; }
            else {
                Tdst[o]      = 2.f * s0 - Tprev[o];
                Tdst[o + 32] = 2.f * s1 - Tprev[o + 32];
            }
        }
    };

    matmul(S0, 0, c[0]);
    prop(S0, nullptr, S1, true);
    matmul(S1, 1, c[1]);
    __syncthreads();
    prop(S1, S0, S2, false);
    matmul(S2, 2, c[2]);
    __syncthreads();
    prop(S2, S1, S0, false);
    matmul(S0, 3, c[3]);

    float bc0 = bch[lane], bc1 = bch[lane + 32];
    for (int i = 0; i < 16; i++) {
        int n = i * 16 + w;
        size_t base = ((size_t)(n * 64 + b)) * ND + h * 64;
        g_filt[base + lane]      = acc0[i] + bc0;
        g_filt[base + lane + 32] = acc1[i] + bc1;
    }
}

// ---------------- stage 4a: 3xTF32 tensor-core GEMM ----------------
// C[16384,512] = concat(outp, g_filt)[16384,1024] @ W_cat[1024,512]
// BM=128 BN=128 BK=16, 256 threads = 8 warps (2x4), warp tile 64x32.

__device__ __forceinline__ unsigned f2tf32(float x) {
    unsigned r;
    asm("cvt.rna.tf32.f32 %0, %1;" : "=r"(r) : "f"(x));
    return r;
}

__device__ __forceinline__ void mma_tf32(float* c, const unsigned* a, const unsigned* b) {
    asm volatile(
        "mma.sync.aligned.m16n8k8.row.col.f32.tf32.tf32.f32 "
        "{%0,%1,%2,%3}, {%4,%5,%6,%7}, {%8,%9}, {%0,%1,%2,%3};"
        : "+f"(c[0]), "+f"(c[1]), "+f"(c[2]), "+f"(c[3])
        : "r"(a[0]), "r"(a[1]), "r"(a[2]), "r"(a[3]), "r"(b[0]), "r"(b[1]));
}

#define AST 20     // A smem stride: [m][k], 16+4 pad -> conflict-free frag loads
#define BST 132    // B smem stride: [k][n], 128+4 pad

__global__ void __launch_bounds__(256) k_gemm(const float* __restrict__ outp,
                                              const float* __restrict__ Wc,
                                              float* __restrict__ out) {
    __shared__ unsigned Ah[128 * AST], Al[128 * AST];
    __shared__ unsigned Bh[16 * BST],  Bl[16 * BST];

    int tid  = threadIdx.x;
    int wid  = tid >> 5;
    int lane = tid & 31;
    int wm   = wid >> 2;          // 0..1 (rows)
    int wn   = wid & 3;           // 0..3 (cols)
    int m0   = blockIdx.x * 128;
    int n0   = blockIdx.y * 128;

    float acc[4][4][4];
#pragma unroll
    for (int mi = 0; mi < 4; mi++)
#pragma unroll
        for (int ni = 0; ni < 4; ni++)
#pragma unroll
            for (int q = 0; q < 4; q++) acc[mi][ni][q] = 0.f;

    // per-thread load roles
    int aRow = tid >> 2;                 // 0..63... need 128 rows, 2 loads
    int aKc  = (tid & 3) * 4;
    int bK   = tid >> 5;                 // 0..7, 2 loads cover 16 rows
    int bN   = (tid & 31) * 4;

    float4 aReg[2], bReg[2];

    auto load_tile = [&](int kb) {
        const float* Asrc = (kb < 32) ? outp : g_filt;
        int ko = (kb < 32) ? kb * 16 : (kb - 32) * 16;
#pragma unroll
        for (int q = 0; q < 2; q++) {
            int row = aRow + q * 64;
            aReg[q] = *(const float4*)(Asrc + (size_t)(m0 + row) * ND + ko + aKc);
        }
#pragma unroll
        for (int q = 0; q < 2; q++) {
            int kk = bK + q * 8;
            bReg[q] = *(const float4*)(Wc + (size_t)(kb * 16 + kk) * ND + n0 + bN);
        }
    };

    auto store_tile = [&]() {
#pragma unroll
        for (int q = 0; q < 2; q++) {
            int row = aRow + q * 64;
            float v[4] = {aReg[q].x, aReg[q].y, aReg[q].z, aReg[q].w};
            unsigned h4[4], l4[4];
#pragma unroll
            for (int j = 0; j < 4; j++) {
                h4[j] = f2tf32(v[j]);
                l4[j] = f2tf32(v[j] - __uint_as_float(h4[j]));
            }
            *(uint4*)&Ah[row * AST + aKc] = make_uint4(h4[0], h4[1], h4[2], h4[3]);
            *(uint4*)&Al[row * AST + aKc] = make_uint4(l4[0], l4[1], l4[2], l4[3]);
        }
#pragma unroll
        for (int q = 0; q < 2; q++) {
            int kk = bK + q * 8;
            float v[4] = {bReg[q].x, bReg[q].y, bReg[q].z, bReg[q].w};
            unsigned h4[4], l4[4];
#pragma unroll
            for (int j = 0; j < 4; j++) {
                h4[j] = f2tf32(v[j]);
                l4[j] = f2tf32(v[j] - __uint_as_float(h4[j]));
            }
            *(uint4*)&Bh[kk * BST + bN] = make_uint4(h4[0], h4[1], h4[2], h4[3]);
            *(uint4*)&Bl[kk * BST + bN] = make_uint4(l4[0], l4[1], l4[2], l4[3]);
        }
    };

    load_tile(0);
    int r = lane >> 2, cl = lane & 3;

    for (int kb = 0; kb < 64; kb++) {
        store_tile();
        __syncthreads();
        if (kb + 1 < 64) load_tile(kb + 1);   // LDGs in flight during compute

#pragma unroll
        for (int s = 0; s < 2; s++) {
            int k = s * 8 + cl;
            unsigned ah[4][4], al[4][4], bh[4][2], bl[4][2];
#pragma unroll
            for (int mi = 0; mi < 4; mi++) {
                int m = wm * 64 + mi * 16 + r;
                ah[mi][0] = Ah[m * AST + k];
                ah[mi][1] = Ah[(m + 8) * AST + k];
                ah[mi][2] = Ah[m * AST + k + 4];
                ah[mi][3] = Ah[(m + 8) * AST + k + 4];
                al[mi][0] = Al[m * AST + k];
                al[mi][1] = Al[(m + 8) * AST + k];
                al[mi][2] = Al[m * AST + k + 4];
                al[mi][3] = Al[(m + 8) * AST + k + 4];
            }
#pragma unroll
            for (int ni = 0; ni < 4; ni++) {
                int n = wn * 32 + ni * 8 + r;
                bh[ni][0] = Bh[k * BST + n];
                bh[ni][1] = Bh[(k + 4) * BST + n];   // note: k+4 row, same n
                bl[ni][0] = Bl[k * BST + n];
                bl[ni][1] = Bl[(k + 4) * BST + n];
            }
#pragma unroll
            for (int mi = 0; mi < 4; mi++)
#pragma unroll
                for (int ni = 0; ni < 4; ni++) {
                    mma_tf32(acc[mi][ni], ah[mi], bh[ni]);
                    mma_tf32(acc[mi][ni], ah[mi], bl[ni]);
                    mma_tf32(acc[mi][ni], al[mi], bh[ni]);
                }
        }
        __syncthreads();
    }

    // write raw GEMM result (bias + LN fused in k_ln)
#pragma unroll
    for (int mi = 0; mi < 4; mi++) {
#pragma unroll
        for (int ni = 0; ni < 4; ni++) {
            int row = m0 + wm * 64 + mi * 16 + r;
            int col = n0 + wn * 32 + ni * 8 + cl * 2;
            *(float2*)(out + (size_t)row * ND + col)       = make_float2(acc[mi][ni][0], acc[mi][ni][1]);
            *(float2*)(out + (size_t)(row + 8) * ND + col) = make_float2(acc[mi][ni][2], acc[mi][ni][3]);
        }
    }
}

// ---------------- stage 4b: bias + LayerNorm (in-place over out) ----------------
__global__ void __launch_bounds__(256) k_ln(const float* __restrict__ bc,
                                            const float* __restrict__ gamma,
                                            const float* __restrict__ beta,
                                            float* __restrict__ out) {
    __shared__ float sb[ND], sg[ND], sbe[ND];
    int tid = threadIdx.x;
#pragma unroll
    for (int q = 0; q < 2; q++) {
        int i = tid + q * 256;
        sb[i] = bc[i]; sg[i] = gamma[i]; sbe[i] = beta[i];
    }
    __syncthreads();

    int lane = tid & 31;
    int wrp  = tid >> 5;
    int row  = blockIdx.x * 8 + wrp;

    float* rp = out + (size_t)row * ND;
    float v[16];
    float s = 0.f, sq = 0.f;
#pragma unroll
    for (int q = 0; q < 4; q++) {
        int c = lane * 4 + q * 128;
        float4 x = *(const float4*)(rp + c);
        float4 bb = *(const float4*)(sb + c);
        v[q * 4 + 0] = x.x + bb.x;
        v[q * 4 + 1] = x.y + bb.y;
        v[q * 4 + 2] = x.z + bb.z;
        v[q * 4 + 3] = x.w + bb.w;
#pragma unroll
        for (int j = 0; j < 4; j++) {
            s  += v[q * 4 + j];
            sq += v[q * 4 + j] * v[q * 4 + j];
        }
    }
#pragma unroll
    for (int off = 16; off > 0; off >>= 1) {
        s  += __shfl_xor_sync(0xffffffffu, s, off);
        sq += __shfl_xor_sync(0xffffffffu, sq, off);
    }
    float mu  = s * (1.0f / 512.0f);
    float var = sq * (1.0f / 512.0f) - mu * mu;
    float rstd = rsqrtf(var + 1e-5f);
#pragma unroll
    for (int q = 0; q < 4; q++) {
        int c = lane * 4 + q * 128;
        float4 gg = *(const float4*)(sg + c);
        float4 be = *(const float4*)(sbe + c);
        float4 o;
        o.x = (v[q * 4 + 0] - mu) * rstd * gg.x + be.x;
        o.y = (v[q * 4 + 1] - mu) * rstd * gg.y + be.y;
        o.z = (v[q * 4 + 2] - mu) * rstd * gg.z + be.z;
        o.w = (v[q * 4 + 3] - mu) * rstd * gg.w + be.w;
        *(float4*)(rp + c) = o;
    }
}

// ---------------- launch ----------------
extern "C" void kernel_launch(void* const* d_in, const int* in_sizes, int n_in,
                              void* d_out, int out_size) {
    const float* outp  = (const float*)d_in[0];
    const float* attn  = (const float*)d_in[1];
    const float* oeh   = (const float*)d_in[2];
    const void*  ei    = d_in[3];
    const float* Wg    = (const float*)d_in[6];
    const float* bg    = (const float*)d_in[7];
    const float* Wl    = (const float*)d_in[8];
    const float* bl    = (const float*)d_in[9];
    const float* Wch   = (const float*)d_in[10];
    const float* bch   = (const float*)d_in[11];
    const float* Wc    = (const float*)d_in[12];
    const float* bc    = (const float*)d_in[13];
    const float* gamma = (const float*)d_in[14];
    const float* beta  = (const float*)d_in[15];
    float* out = (float*)d_out;

    cudaFuncSetAttribute(k_cheb, cudaFuncAttributeMaxDynamicSharedMemorySize, 3 * NN * NDH * 4);

    k_detect<<<1, 32>>>((const int*)ei);
    k_coeff<<<NG, 256>>>(attn, Wg, bg, Wl, bl);
    k_zero<<<NTOT / 256, 256>>>();
    k_degk<<<NE / 256, 256>>>(ei);
    k_scan<<<1, 512>>>();
    k_scatter<<<NE / 256, 256>>>(ei);
    k_cheb<<<NG, 512, 3 * NN * NDH * 4>>>(oeh, Wch, bch);
    dim3 gg2(128, 4);
    k_gemm<<<gg2, 256>>>(outp, Wc, out);
    k_ln<<<NTOT / 8, 256>>>(bc, gamma, beta, out);
}

// round 3
// speedup vs baseline: 1.4971x; 1.2617x over previous
#include <cuda_runtime.h>
#include <cuda_bf16.h>

// Problem constants
#define NB   64
#define NN   256
#define NH   8
#define NDH  64
#define ND   512
#define NK   1024       // 2*D concat width
#define NTOT 16384      // B*N
#define NE   262144     // TOTAL*DEG
#define NG   512        // H*B graphs

// ---------------- device scratch ----------------
__device__ int            g_is64;
__device__ float          g_coeff[NG * 4];
__device__ float          g_dinv[NTOT];
__device__ int            g_deg[NTOT];
__device__ int            g_off[NTOT + 1];
__device__ int            g_cur[NTOT];
__device__ unsigned short g_esrc[NE];
__device__ float          g_enorm[NE];
// bf16 hi/lo A = [outp | cheb_filtered]  (rows in (n,b) order), and W_cat hi/lo
__device__ __nv_bfloat16  g_Ahi[(size_t)NTOT * NK];
__device__ __nv_bfloat16  g_Alo[(size_t)NTOT * NK];
__device__ __nv_bfloat16  g_Bhi[(size_t)NK * ND];
__device__ __nv_bfloat16  g_Blo[(size_t)NK * ND];

__device__ __forceinline__ __nv_bfloat16 bfhi(float x) { return __float2bfloat16_rn(x); }

// ---------------- edge dtype detection ----------------
__global__ void k_detect(const int* p) {
    if (blockIdx.x == 0 && threadIdx.x == 0) {
        int ok64 = 1;
        for (int q = 1; q < 64; q += 2)
            if (p[q] != 0) ok64 = 0;
        g_is64 = ok64;
    }
}

__device__ __forceinline__ void load_edge(const void* ei, int e, int& s, int& d) {
    if (g_is64) {
        const long long* p = (const long long*)ei;
        s = (int)p[e];
        d = (int)p[NE + e];
    } else {
        const int* p = (const int*)ei;
        s = p[e];
        d = p[NE + e];
    }
}

// ---------------- stage 1: GCN coeff per graph ----------------
__global__ void __launch_bounds__(256) k_coeff(const float* __restrict__ attn,
                                               const float* __restrict__ Wg,
                                               const float* __restrict__ bg,
                                               const float* __restrict__ Wl,
                                               const float* __restrict__ bl) {
    int g = blockIdx.x;
    int h = g >> 6;
    int b = g & 63;
    const float* A = attn + ((size_t)b * NH + h) * (NN * NN);
    int j = threadIdx.x;

    __shared__ float dsm[NN];
    __shared__ float red[4];

    float cs = 0.f;
#pragma unroll 8
    for (int i = 0; i < NN; i++) cs += A[i * NN + j];
    float deg = cs + 1.0f;
    float dv = (deg > 0.f) ? rsqrtf(deg) : 0.f;
    dsm[j] = dv;
    if (j < 4) red[j] = 0.f;
    __syncthreads();

    float t = 0.f;
#pragma unroll 8
    for (int i = 0; i < NN; i++) t += dsm[i] * A[i * NN + j];
    float sj = (t + dv) * dv;

    float w_row[4], v[4];
#pragma unroll
    for (int c = 0; c < 4; c++)
        w_row[c] = Wg[c] + Wg[4 + c] + Wg[8 + c] + Wg[12 + c];
#pragma unroll
    for (int c = 0; c < 4; c++)
        v[c] = tanhf(sj * w_row[c] + bg[c]);

#pragma unroll
    for (int c = 0; c < 4; c++) {
#pragma unroll
        for (int off = 16; off > 0; off >>= 1)
            v[c] += __shfl_xor_sync(0xffffffffu, v[c], off);
    }
    if ((j & 31) == 0) {
#pragma unroll
        for (int c = 0; c < 4; c++) atomicAdd(&red[c], v[c]);
    }
    __syncthreads();

    if (j == 0) {
        float gap[4];
#pragma unroll
        for (int c = 0; c < 4; c++) gap[c] = red[c] * (1.0f / 256.0f);
#pragma unroll
        for (int c2 = 0; c2 < 4; c2++) {
            float cc = bl[c2];
#pragma unroll
            for (int c = 0; c < 4; c++) cc += gap[c] * Wl[c * 4 + c2];
            g_coeff[g * 4 + c2] = cc;
        }
    }
}

// ---------------- stage 2: edge CSR build ----------------
__global__ void k_zero() {
    int i = blockIdx.x * blockDim.x + threadIdx.x;
    if (i < NTOT) { g_deg[i] = 0; g_cur[i] = 0; }
}

__global__ void k_degk(const void* ei) {
    int e = blockIdx.x * blockDim.x + threadIdx.x;
    if (e < NE) {
        int s, d;
        load_edge(ei, e, s, d);
        atomicAdd(&g_deg[d], 1);
    }
}

__global__ void __launch_bounds__(512) k_scan() {
    __shared__ int sc[512];
    int t = threadIdx.x;
    int base = t * 32;
    int sum = 0;
    for (int i = 0; i < 32; i++) {
        int d = g_deg[base + i];
        g_dinv[base + i] = (d > 0) ? rsqrtf((float)d) : 0.f;
        sum += d;
    }
    sc[t] = sum;
    __syncthreads();
    for (int off = 1; off < 512; off <<= 1) {
        int v = sc[t];
        int u = (t >= off) ? sc[t - off] : 0;
        __syncthreads();
        sc[t] = v + u;
        __syncthreads();
    }
    int run = sc[t] - sum;
    for (int i = 0; i < 32; i++) {
        g_off[base + i] = run;
        run += g_deg[base + i];
    }
    if (t == 511) g_off[NTOT] = sc[511];
}

__global__ void k_scatter(const void* ei) {
    int e = blockIdx.x * blockDim.x + threadIdx.x;
    if (e < NE) {
        int s, d;
        load_edge(ei, e, s, d);
        float nm = -(g_dinv[s] * g_dinv[d]);
        int pos = g_off[d] + atomicAdd(&g_cur[d], 1);
        g_esrc[pos]  = (unsigned short)(s & (NN - 1));
        g_enorm[pos] = nm;
    }
}

// ---------------- prep: fp32 -> bf16 hi/lo ----------------
// A columns 0..511 from outp (rows already in (n,b) order)
__global__ void __launch_bounds__(256) k_prepA(const float* __restrict__ outp) {
    int idx = blockIdx.x * 256 + threadIdx.x;       // one float4 per thread
    int row = idx >> 7;                             // 512/4 = 128 groups per row
    int c4  = (idx & 127) * 4;
    float4 x = *(const float4*)(outp + (size_t)row * ND + c4);
    float v[4] = {x.x, x.y, x.z, x.w};
    __nv_bfloat16 h[4], l[4];
#pragma unroll
    for (int j = 0; j < 4; j++) {
        h[j] = bfhi(v[j]);
        l[j] = bfhi(v[j] - __bfloat162float(h[j]));
    }
    size_t o = (size_t)row * NK + c4;
    *(uint2*)(g_Ahi + o) = *(uint2*)h;
    *(uint2*)(g_Alo + o) = *(uint2*)l;
}

__global__ void __launch_bounds__(256) k_prepW(const float* __restrict__ Wc) {
    int idx = blockIdx.x * 256 + threadIdx.x;
    float4 x = *(const float4*)(Wc + (size_t)idx * 4);
    float v[4] = {x.x, x.y, x.z, x.w};
    __nv_bfloat16 h[4], l[4];
#pragma unroll
    for (int j = 0; j < 4; j++) {
        h[j] = bfhi(v[j]);
        l[j] = bfhi(v[j] - __bfloat162float(h[j]));
    }
    *(uint2*)(g_Bhi + (size_t)idx * 4) = *(uint2*)h;
    *(uint2*)(g_Blo + (size_t)idx * 4) = *(uint2*)l;
}

// ---------------- stage 3: Chebyshev propagation + per-head matmul ----------------
__global__ void __launch_bounds__(512, 1) k_cheb(const float* __restrict__ oeh,
                                                 const float* __restrict__ Wch,
                                                 const float* __restrict__ bch) {
    extern __shared__ float sm[];
    float* S0 = sm;
    float* S1 = sm + NN * NDH;
    float* S2 = sm + 2 * NN * NDH;

    int g = blockIdx.x;
    int h = g >> 6;
    int b = g & 63;
    int tid = threadIdx.x;
    int w = tid >> 5;
    int lane = tid & 31;

    const float* xb = oeh + (size_t)b * 131072 + (size_t)h * 64;
    for (int idx = tid; idx < NN * NDH; idx += 512) {
        int n = idx >> 6, d = idx & 63;
        S0[idx] = xb[(size_t)n * 512 + d];
    }

    float c[4];
#pragma unroll
    for (int k = 0; k < 4; k++) c[k] = g_coeff[g * 4 + k];

    float acc0[16], acc1[16];
#pragma unroll
    for (int i = 0; i < 16; i++) { acc0[i] = 0.f; acc1[i] = 0.f; }

    __syncthreads();

    auto matmul = [&](const float* T, int k, float ck) {
        const float* Wk = Wch + k * 4096;
        for (int jc = 0; jc < 64; jc += 16) {
            float W0[16], W1[16];
#pragma unroll
            for (int jj = 0; jj < 16; jj++) {
                W0[jj] = ck * Wk[(jc + jj) * 64 + lane];
                W1[jj] = ck * Wk[(jc + jj) * 64 + lane + 32];
            }
#pragma unroll 4
            for (int jj = 0; jj < 16; jj++) {
                int j = jc + jj;
#pragma unroll
                for (int i = 0; i < 16; i++) {
                    float tv = T[(i * 16 + w) * 64 + j];
                    acc0[i] += tv * W0[jj];
                    acc1[i] += tv * W1[jj];
                }
            }
        }
    };

    auto prop = [&](const float* Tsrc, const float* Tprev, float* Tdst, bool first) {
        for (int i = 0; i < 16; i++) {
            int n = i * 16 + w;
            int dn = b * NN + n;
            int eb = g_off[dn], ee = g_off[dn + 1];
            float s0 = 0.f, s1 = 0.f;
            for (int e0 = eb; e0 < ee; e0 += 32) {
                int me = e0 + lane;
                int sl = 0; float wn = 0.f;
                if (me < ee) { sl = g_esrc[me]; wn = g_enorm[me]; }
                int cnt = min(32, ee - e0);
                for (int q = 0; q < cnt; q++) {
                    int ss  = __shfl_sync(0xffffffffu, sl, q);
                    float ww = __shfl_sync(0xffffffffu, wn, q);
                    s0 += ww * Tsrc[ss * 64 + lane];
                    s1 += ww * Tsrc[ss * 64 + lane + 32];
                }
            }
            int o = n * 64 + lane;
            if (first) { Tdst[o] = s0; Tdst[o + 32] = s1; }
            else {
                Tdst[o]      = 2.f * s0 - Tprev[o];
                Tdst[o + 32] = 2.f * s1 - Tprev[o + 32];
            }
        }
    };

    matmul(S0, 0, c[0]);
    prop(S0, nullptr, S1, true);
    matmul(S1, 1, c[1]);
    __syncthreads();
    prop(S1, S0, S2, false);
    matmul(S2, 2, c[2]);
    __syncthreads();
    prop(S2, S1, S0, false);
    matmul(S0, 3, c[3]);

    float bc0 = bch[lane], bc1 = bch[lane + 32];
    for (int i = 0; i < 16; i++) {
        int n = i * 16 + w;
        size_t base = ((size_t)(n * 64 + b)) * NK + 512 + h * 64;   // A cols 512+
        float v0 = acc0[i] + bc0;
        float v1 = acc1[i] + bc1;
        __nv_bfloat16 h0 = bfhi(v0);
        __nv_bfloat16 h1 = bfhi(v1);
        g_Ahi[base + lane]      = h0;
        g_Ahi[base + lane + 32] = h1;
        g_Alo[base + lane]      = bfhi(v0 - __bfloat162float(h0));
        g_Alo[base + lane + 32] = bfhi(v1 - __bfloat162float(h1));
    }
}

// ---------------- stage 4a: 3x-bf16 tensor-core GEMM ----------------
// out[16384,512] = A[16384,1024] @ W[1024,512]  via AhBh + AhBl + AlBh
// BM=128 BN=128 BK=32, 256 threads = 8 warps (2x4), warp tile 64x32.

#define ASTRIDE 40     // 32 + 8 pad (bf16 el), 80B rows -> conflict-free LDSM
#define BSTRIDE 136    // 128 + 8 pad, 272B rows -> conflict-free LDSM
#define A_BUF   (128 * ASTRIDE)   // 5120 el
#define B_BUF   (32 * BSTRIDE)    // 4352 el

__device__ __forceinline__ void cp16(void* smem_dst, const void* gmem_src) {
    unsigned s = (unsigned)__cvta_generic_to_shared(smem_dst);
    asm volatile("cp.async.cg.shared.global [%0], [%1], 16;" :: "r"(s), "l"(gmem_src));
}
__device__ __forceinline__ void cp_commit() { asm volatile("cp.async.commit_group;"); }
template <int N>
__device__ __forceinline__ void cp_wait() { asm volatile("cp.async.wait_group %0;" :: "n"(N)); }

__device__ __forceinline__ void ldsm4(unsigned* r, const void* p) {
    unsigned s = (unsigned)__cvta_generic_to_shared(p);
    asm volatile("ldmatrix.sync.aligned.m8n8.x4.shared.b16 {%0,%1,%2,%3}, [%4];"
                 : "=r"(r[0]), "=r"(r[1]), "=r"(r[2]), "=r"(r[3]) : "r"(s));
}
__device__ __forceinline__ void ldsm4t(unsigned* r, const void* p) {
    unsigned s = (unsigned)__cvta_generic_to_shared(p);
    asm volatile("ldmatrix.sync.aligned.m8n8.x4.trans.shared.b16 {%0,%1,%2,%3}, [%4];"
                 : "=r"(r[0]), "=r"(r[1]), "=r"(r[2]), "=r"(r[3]) : "r"(s));
}
__device__ __forceinline__ void mma_bf16(float* c, const unsigned* a, const unsigned* b) {
    asm volatile(
        "mma.sync.aligned.m16n8k16.row.col.f32.bf16.bf16.f32 "
        "{%0,%1,%2,%3}, {%4,%5,%6,%7}, {%8,%9}, {%0,%1,%2,%3};"
        : "+f"(c[0]), "+f"(c[1]), "+f"(c[2]), "+f"(c[3])
        : "r"(a[0]), "r"(a[1]), "r"(a[2]), "r"(a[3]), "r"(b[0]), "r"(b[1]));
}

__global__ void __launch_bounds__(256) k_gemm(float* __restrict__ out) {
    extern __shared__ __nv_bfloat16 sh[];
    __nv_bfloat16* sAh = sh;                       // [2][A_BUF]
    __nv_bfloat16* sAl = sh + 2 * A_BUF;           // [2][A_BUF]
    __nv_bfloat16* sBh = sh + 4 * A_BUF;           // [2][B_BUF]
    __nv_bfloat16* sBl = sh + 4 * A_BUF + 2 * B_BUF;

    int tid  = threadIdx.x;
    int wid  = tid >> 5;
    int lane = tid & 31;
    int wm   = wid >> 2;
    int wn   = wid & 3;
    int m0   = blockIdx.x * 128;
    int n0   = blockIdx.y * 128;

    float acc[4][4][4];
#pragma unroll
    for (int mi = 0; mi < 4; mi++)
#pragma unroll
        for (int nj = 0; nj < 4; nj++)
#pragma unroll
            for (int q = 0; q < 4; q++) acc[mi][nj][q] = 0.f;

    auto load_stage = [&](int kb, int buf) {
#pragma unroll
        for (int q = 0; q < 2; q++) {
            int c = tid + q * 256;
            int row = c >> 2, seg = (c & 3) * 8;
            size_t go = (size_t)(m0 + row) * NK + kb * 32 + seg;
            int so = buf * A_BUF + row * ASTRIDE + seg;
            cp16(sAh + so, g_Ahi + go);
            cp16(sAl + so, g_Alo + go);
        }
#pragma unroll
        for (int q = 0; q < 2; q++) {
            int c = tid + q * 256;
            int row = c >> 4, seg = (c & 15) * 8;
            size_t go = (size_t)(kb * 32 + row) * ND + n0 + seg;
            int so = buf * B_BUF + row * BSTRIDE + seg;
            cp16(sBh + so, g_Bhi + go);
            cp16(sBl + so, g_Blo + go);
        }
    };

    load_stage(0, 0);
    cp_commit();

    int aRow = lane & 15, aCol = (lane >> 4) * 8;
    int bRow = lane & 15, bCol = (lane >> 4) * 8;
    int buf = 0;

    for (int kb = 0; kb < 32; kb++) {
        if (kb + 1 < 32) { load_stage(kb + 1, buf ^ 1); cp_commit(); cp_wait<1>(); }
        else             { cp_wait<0>(); }
        __syncthreads();

        const __nv_bfloat16* pAh = sAh + buf * A_BUF;
        const __nv_bfloat16* pAl = sAl + buf * A_BUF;
        const __nv_bfloat16* pBh = sBh + buf * B_BUF;
        const __nv_bfloat16* pBl = sBl + buf * B_BUF;

#pragma unroll
        for (int step = 0; step < 2; step++) {
            int k0 = step * 16;
            unsigned ah[4][4], al[4][4], bh[2][4], bl[2][4];
#pragma unroll
            for (int mi = 0; mi < 4; mi++) {
                int m = wm * 64 + mi * 16 + aRow;
                ldsm4(ah[mi], pAh + m * ASTRIDE + k0 + aCol);
                ldsm4(al[mi], pAl + m * ASTRIDE + k0 + aCol);
            }
#pragma unroll
            for (int ng = 0; ng < 2; ng++) {
                int n = wn * 32 + ng * 16 + bCol;
                ldsm4t(bh[ng], pBh + (k0 + bRow) * BSTRIDE + n);
                ldsm4t(bl[ng], pBl + (k0 + bRow) * BSTRIDE + n);
            }
#pragma unroll
            for (int mi = 0; mi < 4; mi++)
#pragma unroll
                for (int ng = 0; ng < 2; ng++)
#pragma unroll
                    for (int hf = 0; hf < 2; hf++) {
                        int nj = ng * 2 + hf;
                        unsigned bhf[2] = {bh[ng][hf * 2], bh[ng][hf * 2 + 1]};
                        unsigned blf[2] = {bl[ng][hf * 2], bl[ng][hf * 2 + 1]};
                        mma_bf16(acc[mi][nj], ah[mi], bhf);
                        mma_bf16(acc[mi][nj], ah[mi], blf);
                        mma_bf16(acc[mi][nj], al[mi], bhf);
                    }
        }
        __syncthreads();
        buf ^= 1;
    }

    int r = lane >> 2, cl = lane & 3;
#pragma unroll
    for (int mi = 0; mi < 4; mi++) {
#pragma unroll
        for (int nj = 0; nj < 4; nj++) {
            int row = m0 + wm * 64 + mi * 16 + r;
            int col = n0 + wn * 32 + nj * 8 + cl * 2;
            *(float2*)(out + (size_t)row * ND + col)       = make_float2(acc[mi][nj][0], acc[mi][nj][1]);
            *(float2*)(out + (size_t)(row + 8) * ND + col) = make_float2(acc[mi][nj][2], acc[mi][nj][3]);
        }
    }
}

// ---------------- stage 4b: bias + LayerNorm (in-place over out) ----------------
__global__ void __launch_bounds__(256) k_ln(const float* __restrict__ bc,
                                            const float* __restrict__ gamma,
                                            const float* __restrict__ beta,
                                            float* __restrict__ out) {
    __shared__ float sb[ND], sg[ND], sbe[ND];
    int tid = threadIdx.x;
#pragma unroll
    for (int q = 0; q < 2; q++) {
        int i = tid + q * 256;
        sb[i] = bc[i]; sg[i] = gamma[i]; sbe[i] = beta[i];
    }
    __syncthreads();

    int lane = tid & 31;
    int wrp  = tid >> 5;
    int row  = blockIdx.x * 8 + wrp;

    float* rp = out + (size_t)row * ND;
    float v[16];
    float s = 0.f, sq = 0.f;
#pragma unroll
    for (int q = 0; q < 4; q++) {
        int c = lane * 4 + q * 128;
        float4 x = *(const float4*)(rp + c);
        float4 bb = *(const float4*)(sb + c);
        v[q * 4 + 0] = x.x + bb.x;
        v[q * 4 + 1] = x.y + bb.y;
        v[q * 4 + 2] = x.z + bb.z;
        v[q * 4 + 3] = x.w + bb.w;
#pragma unroll
        for (int j = 0; j < 4; j++) {
            s  += v[q * 4 + j];
            sq += v[q * 4 + j] * v[q * 4 + j];
        }
    }
#pragma unroll
    for (int off = 16; off > 0; off >>= 1) {
        s  += __shfl_xor_sync(0xffffffffu, s, off);
        sq += __shfl_xor_sync(0xffffffffu, sq, off);
    }
    float mu  = s * (1.0f / 512.0f);
    float var = sq * (1.0f / 512.0f) - mu * mu;
    float rstd = rsqrtf(var + 1e-5f);
#pragma unroll
    for (int q = 0; q < 4; q++) {
        int c = lane * 4 + q * 128;
        float4 gg = *(const float4*)(sg + c);
        float4 be = *(const float4*)(sbe + c);
        float4 o;
        o.x = (v[q * 4 + 0] - mu) * rstd * gg.x + be.x;
        o.y = (v[q * 4 + 1] - mu) * rstd * gg.y + be.y;
        o.z = (v[q * 4 + 2] - mu) * rstd * gg.z + be.z;
        o.w = (v[q * 4 + 3] - mu) * rstd * gg.w + be.w;
        *(float4*)(rp + c) = o;
    }
}

// ---------------- launch ----------------
extern "C" void kernel_launch(void* const* d_in, const int* in_sizes, int n_in,
                              void* d_out, int out_size) {
    const float* outp  = (const float*)d_in[0];
    const float* attn  = (const float*)d_in[1];
    const float* oeh   = (const float*)d_in[2];
    const void*  ei    = d_in[3];
    const float* Wg    = (const float*)d_in[6];
    const float* bg    = (const float*)d_in[7];
    const float* Wl    = (const float*)d_in[8];
    const float* bl    = (const float*)d_in[9];
    const float* Wch   = (const float*)d_in[10];
    const float* bch   = (const float*)d_in[11];
    const float* Wc    = (const float*)d_in[12];
    const float* bc    = (const float*)d_in[13];
    const float* gamma = (const float*)d_in[14];
    const float* beta  = (const float*)d_in[15];
    float* out = (float*)d_out;

    cudaFuncSetAttribute(k_cheb, cudaFuncAttributeMaxDynamicSharedMemorySize, 3 * NN * NDH * 4);
    int gemm_smem = (4 * A_BUF + 4 * B_BUF) * 2;   // bytes
    cudaFuncSetAttribute(k_gemm, cudaFuncAttributeMaxDynamicSharedMemorySize, gemm_smem);

    k_detect<<<1, 32>>>((const int*)ei);
    k_coeff<<<NG, 256>>>(attn, Wg, bg, Wl, bl);
    k_zero<<<NTOT / 256, 256>>>();
    k_degk<<<NE / 256, 256>>>(ei);
    k_scan<<<1, 512>>>();
    k_scatter<<<NE / 256, 256>>>(ei);
    k_prepA<<<NTOT * (ND / 4) / 256, 256>>>(outp);
    k_prepW<<<(NK * ND / 4) / 256, 256>>>(Wc);
    k_cheb<<<NG, 512, 3 * NN * NDH * 4>>>(oeh, Wch, bch);
    dim3 gg2(128, 4);
    k_gemm<<<gg2, 256, gemm_smem>>>(out);
    k_ln<<<NTOT / 8, 256>>>(bc, gamma, beta, out);
}

// round 5
// speedup vs baseline: 1.8184x; 1.2146x over previous
#include <cuda_runtime.h>
#include <cuda_bf16.h>

// Problem constants
#define NB   64
#define NN   256
#define NH   8
#define NDH  64
#define ND   512
#define NK   1024       // 2*D concat width
#define NTOT 16384      // B*N
#define NE   262144     // TOTAL*DEG
#define NG   512        // H*B graphs
#define TST  68         // T-buffer row stride (floats), padded vs 64 for banks

// ---------------- device scratch ----------------
__device__ int            g_is64;
__device__ float          g_coeff[NG * 4];
__device__ float          g_dinv[NTOT];
__device__ int            g_deg[NTOT];
__device__ int            g_off[NTOT + 1];
__device__ int            g_cur[NTOT];
__device__ int2           g_epack[NE];            // {src_local, norm_bits}
// bf16 hi/lo A = [outp | cheb_filtered]  (rows in (n,b) order), and W_cat hi/lo
__device__ __nv_bfloat16  g_Ahi[(size_t)NTOT * NK];
__device__ __nv_bfloat16  g_Alo[(size_t)NTOT * NK];
__device__ __nv_bfloat16  g_Bhi[(size_t)NK * ND];
__device__ __nv_bfloat16  g_Blo[(size_t)NK * ND];
// W_cheb in mma-fragment-linear order: idx = (((k*4+kt)*8+nt)*32+lane), uint2 per idx
__device__ uint2          g_Wfh[4 * 4 * 8 * 32];
__device__ uint2          g_Wfl[4 * 4 * 8 * 32];

__device__ __forceinline__ __nv_bfloat16 bfhi(float x) { return __float2bfloat16_rn(x); }

__device__ __forceinline__ void cvt_hilo(float x, float y, unsigned& h, unsigned& l) {
    __nv_bfloat16 hx = __float2bfloat16_rn(x);
    __nv_bfloat16 hy = __float2bfloat16_rn(y);
    h = (unsigned)__bfloat16_as_ushort(hx) | ((unsigned)__bfloat16_as_ushort(hy) << 16);
    __nv_bfloat16 lx = __float2bfloat16_rn(x - __bfloat162float(hx));
    __nv_bfloat16 ly = __float2bfloat16_rn(y - __bfloat162float(hy));
    l = (unsigned)__bfloat16_as_ushort(lx) | ((unsigned)__bfloat16_as_ushort(ly) << 16);
}

// ---------------- edge dtype detection ----------------
__global__ void k_detect(const int* p) {
    if (blockIdx.x == 0 && threadIdx.x == 0) {
        int ok64 = 1;
        for (int q = 1; q < 64; q += 2)
            if (p[q] != 0) ok64 = 0;
        g_is64 = ok64;
    }
}

__device__ __forceinline__ void load_edge(const void* ei, int e, int& s, int& d) {
    if (g_is64) {
        const long long* p = (const long long*)ei;
        s = (int)p[e];
        d = (int)p[NE + e];
    } else {
        const int* p = (const int*)ei;
        s = p[e];
        d = p[NE + e];
    }
}

// ---------------- stage 1: GCN coeff per graph ----------------
__global__ void __launch_bounds__(256) k_coeff(const float* __restrict__ attn,
                                               const float* __restrict__ Wg,
                                               const float* __restrict__ bg,
                                               const float* __restrict__ Wl,
                                               const float* __restrict__ bl) {
    int g = blockIdx.x;
    int h = g >> 6;
    int b = g & 63;
    const float* A = attn + ((size_t)b * NH + h) * (NN * NN);
    int j = threadIdx.x;

    __shared__ float dsm[NN];
    __shared__ float red[4];

    float cs = 0.f;
#pragma unroll 8
    for (int i = 0; i < NN; i++) cs += A[i * NN + j];
    float deg = cs + 1.0f;
    float dv = (deg > 0.f) ? rsqrtf(deg) : 0.f;
    dsm[j] = dv;
    if (j < 4) red[j] = 0.f;
    __syncthreads();

    float t = 0.f;
#pragma unroll 8
    for (int i = 0; i < NN; i++) t += dsm[i] * A[i * NN + j];
    float sj = (t + dv) * dv;

    float w_row[4], v[4];
#pragma unroll
    for (int c = 0; c < 4; c++)
        w_row[c] = Wg[c] + Wg[4 + c] + Wg[8 + c] + Wg[12 + c];
#pragma unroll
    for (int c = 0; c < 4; c++)
        v[c] = tanhf(sj * w_row[c] + bg[c]);

#pragma unroll
    for (int c = 0; c < 4; c++) {
#pragma unroll
        for (int off = 16; off > 0; off >>= 1)
            v[c] += __shfl_xor_sync(0xffffffffu, v[c], off);
    }
    if ((j & 31) == 0) {
#pragma unroll
        for (int c = 0; c < 4; c++) atomicAdd(&red[c], v[c]);
    }
    __syncthreads();

    if (j == 0) {
        float gap[4];
#pragma unroll
        for (int c = 0; c < 4; c++) gap[c] = red[c] * (1.0f / 256.0f);
#pragma unroll
        for (int c2 = 0; c2 < 4; c2++) {
            float cc = bl[c2];
#pragma unroll
            for (int c = 0; c < 4; c++) cc += gap[c] * Wl[c * 4 + c2];
            g_coeff[g * 4 + c2] = cc;
        }
    }
}

// ---------------- stage 2: edge CSR build ----------------
__global__ void k_zero() {
    int i = blockIdx.x * blockDim.x + threadIdx.x;
    if (i < NTOT) { g_deg[i] = 0; g_cur[i] = 0; }
}

__global__ void k_degk(const void* ei) {
    int e = blockIdx.x * blockDim.x + threadIdx.x;
    if (e < NE) {
        int s, d;
        load_edge(ei, e, s, d);
        atomicAdd(&g_deg[d], 1);
    }
}

__global__ void __launch_bounds__(512) k_scan() {
    __shared__ int sc[512];
    int t = threadIdx.x;
    int base = t * 32;
    int sum = 0;
    for (int i = 0; i < 32; i++) {
        int d = g_deg[base + i];
        g_dinv[base + i] = (d > 0) ? rsqrtf((float)d) : 0.f;
        sum += d;
    }
    sc[t] = sum;
    __syncthreads();
    for (int off = 1; off < 512; off <<= 1) {
        int v = sc[t];
        int u = (t >= off) ? sc[t - off] : 0;
        __syncthreads();
        sc[t] = v + u;
        __syncthreads();
    }
    int run = sc[t] - sum;
    for (int i = 0; i < 32; i++) {
        g_off[base + i] = run;
        run += g_deg[base + i];
    }
    if (t == 511) g_off[NTOT] = sc[511];
}

__global__ void k_scatter(const void* ei) {
    int e = blockIdx.x * blockDim.x + threadIdx.x;
    if (e < NE) {
        int s, d;
        load_edge(ei, e, s, d);
        float nm = -(g_dinv[s] * g_dinv[d]);
        int pos = g_off[d] + atomicAdd(&g_cur[d], 1);
        g_epack[pos] = make_int2(s & (NN - 1), __float_as_int(nm));
    }
}

// ---------------- prep: fp32 -> bf16 hi/lo ----------------
__global__ void __launch_bounds__(256) k_prepA(const float* __restrict__ outp) {
    int idx = blockIdx.x * 256 + threadIdx.x;
    int row = idx >> 7;
    int c4  = (idx & 127) * 4;
    float4 x = *(const float4*)(outp + (size_t)row * ND + c4);
    float v[4] = {x.x, x.y, x.z, x.w};
    __nv_bfloat16 h[4], l[4];
#pragma unroll
    for (int j = 0; j < 4; j++) {
        h[j] = bfhi(v[j]);
        l[j] = bfhi(v[j] - __bfloat162float(h[j]));
    }
    size_t o = (size_t)row * NK + c4;
    *(uint2*)(g_Ahi + o) = *(uint2*)h;
    *(uint2*)(g_Alo + o) = *(uint2*)l;
}

__global__ void __launch_bounds__(256) k_prepW(const float* __restrict__ Wc) {
    int idx = blockIdx.x * 256 + threadIdx.x;
    float4 x = *(const float4*)(Wc + (size_t)idx * 4);
    float v[4] = {x.x, x.y, x.z, x.w};
    __nv_bfloat16 h[4], l[4];
#pragma unroll
    for (int j = 0; j < 4; j++) {
        h[j] = bfhi(v[j]);
        l[j] = bfhi(v[j] - __bfloat162float(h[j]));
    }
    *(uint2*)(g_Bhi + (size_t)idx * 4) = *(uint2*)h;
    *(uint2*)(g_Blo + (size_t)idx * 4) = *(uint2*)l;
}

// W_cheb -> mma fragment-linear hi/lo. One thread per (k,kt,nt,lane).
__global__ void __launch_bounds__(256) k_prepWch(const float* __restrict__ Wch) {
    int i = blockIdx.x * 256 + threadIdx.x;    // 0..4095
    if (i >= 4096) return;
    int lane = i & 31, nt = (i >> 5) & 7, kt = (i >> 8) & 3, k = i >> 10;
    int tt = lane & 3, gg = lane >> 2;
    int n = nt * 8 + gg;
    unsigned h[2], l[2];
#pragma unroll
    for (int reg = 0; reg < 2; reg++) {
        int kr = kt * 16 + 2 * tt + reg * 8;
        float w0 = Wch[k * 4096 + kr * 64 + n];
        float w1 = Wch[k * 4096 + (kr + 1) * 64 + n];
        cvt_hilo(w0, w1, h[reg], l[reg]);
    }
    g_Wfh[i] = make_uint2(h[0], h[1]);
    g_Wfl[i] = make_uint2(l[0], l[1]);
}

// ---------------- mma helpers ----------------
__device__ __forceinline__ void mma_bf16(float* c, const unsigned* a, const unsigned* b) {
    asm volatile(
        "mma.sync.aligned.m16n8k16.row.col.f32.bf16.bf16.f32 "
        "{%0,%1,%2,%3}, {%4,%5,%6,%7}, {%8,%9}, {%0,%1,%2,%3};"
        : "+f"(c[0]), "+f"(c[1]), "+f"(c[2]), "+f"(c[3])
        : "r"(a[0]), "r"(a[1]), "r"(a[2]), "r"(a[3]), "r"(b[0]), "r"(b[1]));
}

// ---------------- stage 3: Chebyshev prop (fp32) + tensor-core matmul ----------------
// One block per graph (h,b). 512 threads = 16 warps; warp w owns nodes [w*16, w*16+16).
// Lane owns feature pair (2*lane, 2*lane+1) in prop. Matmul via mma m16n8k16 bf16 3x.
__global__ void __launch_bounds__(512, 1) k_cheb(const float* __restrict__ oeh,
                                                 const float* __restrict__ bch) {
    extern __shared__ float sm[];
    float* S0 = sm;
    float* S1 = sm + NN * TST;
    float* S2 = sm + 2 * NN * TST;

    int g = blockIdx.x;
    int h = g >> 6;
    int b = g & 63;
    int tid = threadIdx.x;
    int w = tid >> 5;
    int lane = tid & 31;
    int n0 = w * 16;
    int gr = lane >> 2, tt = lane & 3;

    // load x0: oeh[((b*256+n)*8+h)*64+d] -> S0[n*TST+d]
    const float* xb = oeh + (size_t)b * 131072 + (size_t)h * 64;
    for (int idx = tid; idx < NN * NDH; idx += 512) {
        int n = idx >> 6, d = idx & 63;
        S0[n * TST + d] = xb[(size_t)n * 512 + d];
    }

    float c[4];
#pragma unroll
    for (int k = 0; k < 4; k++) c[k] = g_coeff[g * 4 + k];

    float accf[8][4];
#pragma unroll
    for (int nt = 0; nt < 8; nt++)
#pragma unroll
        for (int q = 0; q < 4; q++) accf[nt][q] = 0.f;

    __syncthreads();

    auto matmul = [&](const float* T, int k) {
        float ck = c[k];
#pragma unroll
        for (int kt = 0; kt < 4; kt++) {
            int kc = kt * 16 + 2 * tt;
            float2 x0 = *(const float2*)&T[(n0 + gr) * TST + kc];
            float2 x1 = *(const float2*)&T[(n0 + gr + 8) * TST + kc];
            float2 x2 = *(const float2*)&T[(n0 + gr) * TST + kc + 8];
            float2 x3 = *(const float2*)&T[(n0 + gr + 8) * TST + kc + 8];
            unsigned ah[4], al[4];
            cvt_hilo(ck * x0.x, ck * x0.y, ah[0], al[0]);
            cvt_hilo(ck * x1.x, ck * x1.y, ah[1], al[1]);
            cvt_hilo(ck * x2.x, ck * x2.y, ah[2], al[2]);
            cvt_hilo(ck * x3.x, ck * x3.y, ah[3], al[3]);
            const uint2* WH = g_Wfh + ((k * 4 + kt) * 8) * 32 + lane;
            const uint2* WL = g_Wfl + ((k * 4 + kt) * 8) * 32 + lane;
#pragma unroll
            for (int nt = 0; nt < 8; nt++) {
                uint2 bh = WH[nt * 32];
                uint2 bl = WL[nt * 32];
                unsigned bhv[2] = {bh.x, bh.y};
                unsigned blv[2] = {bl.x, bl.y};
                mma_bf16(accf[nt], ah, bhv);
                mma_bf16(accf[nt], ah, blv);
                mma_bf16(accf[nt], al, bhv);
            }
        }
    };

    auto prop = [&](const float* Tsrc, const float* Tprev, float* Tdst, bool first) {
        for (int i = 0; i < 16; i++) {
            int n = n0 + i;
            int dn = b * NN + n;
            int eb = g_off[dn], ee = g_off[dn + 1];
            float s0a = 0.f, s1a = 0.f, s0b = 0.f, s1b = 0.f;
            int e = eb;
            for (; e + 1 < ee; e += 2) {
                int2 e0 = g_epack[e];
                int2 e1 = g_epack[e + 1];
                float w0 = __int_as_float(e0.y);
                float w1 = __int_as_float(e1.y);
                float2 t0 = *(const float2*)&Tsrc[e0.x * TST + 2 * lane];
                float2 t1 = *(const float2*)&Tsrc[e1.x * TST + 2 * lane];
                s0a += w0 * t0.x; s1a += w0 * t0.y;
                s0b += w1 * t1.x; s1b += w1 * t1.y;
            }
            if (e < ee) {
                int2 e0 = g_epack[e];
                float w0 = __int_as_float(e0.y);
                float2 t0 = *(const float2*)&Tsrc[e0.x * TST + 2 * lane];
                s0a += w0 * t0.x; s1a += w0 * t0.y;
            }
            float s0 = s0a + s0b, s1 = s1a + s1b;
            int o = n * TST + 2 * lane;
            if (first) {
                *(float2*)&Tdst[o] = make_float2(s0, s1);
            } else {
                float2 pv = *(const float2*)&Tprev[o];
                *(float2*)&Tdst[o] = make_float2(2.f * s0 - pv.x, 2.f * s1 - pv.y);
            }
        }
    };

    matmul(S0, 0);                  // k=0 : T0 = x0
    prop(S0, nullptr, S1, true);    // T1 = prop(T0)
    matmul(S1, 1);                  // reads own warp's rows only
    __syncthreads();
    prop(S1, S0, S2, false);        // T2 = 2*prop(T1) - T0
    matmul(S2, 2);
    __syncthreads();
    prop(S2, S1, S0, false);        // T3 = 2*prop(T2) - T1 (overwrite S0, own rows)
    matmul(S0, 3);

    // epilogue: bias + hi/lo bf16 into A cols 512+
#pragma unroll
    for (int nt = 0; nt < 8; nt++) {
        int o = nt * 8 + tt * 2;
        float b0 = bch[o], b1 = bch[o + 1];
        float c0 = accf[nt][0] + b0, c1 = accf[nt][1] + b1;
        float c2 = accf[nt][2] + b0, c3 = accf[nt][3] + b1;
        unsigned h01, l01, h23, l23;
        cvt_hilo(c0, c1, h01, l01);
        cvt_hilo(c2, c3, h23, l23);
        int nA = n0 + gr;
        size_t r1 = (size_t)(nA * 64 + b) * NK + 512 + h * 64 + o;
        size_t r2 = (size_t)((nA + 8) * 64 + b) * NK + 512 + h * 64 + o;
        *(unsigned*)(g_Ahi + r1) = h01;
        *(unsigned*)(g_Alo + r1) = l01;
        *(unsigned*)(g_Ahi + r2) = h23;
        *(unsigned*)(g_Alo + r2) = l23;
    }
}

// ---------------- stage 4a: 3x-bf16 tensor-core GEMM ----------------
#define ASTRIDE 40     // 32 + 8 pad (bf16 el)
#define BSTRIDE 136    // 128 + 8 pad
#define A_BUF   (128 * ASTRIDE)
#define B_BUF   (32 * BSTRIDE)

__device__ __forceinline__ void cp16(void* smem_dst, const void* gmem_src) {
    unsigned s = (unsigned)__cvta_generic_to_shared(smem_dst);
    asm volatile("cp.async.cg.shared.global [%0], [%1], 16;" :: "r"(s), "l"(gmem_src));
}
__device__ __forceinline__ void cp_commit() { asm volatile("cp.async.commit_group;"); }
template <int N>
__device__ __forceinline__ void cp_wait() { asm volatile("cp.async.wait_group %0;" :: "n"(N)); }

__device__ __forceinline__ void ldsm4(unsigned* r, const void* p) {
    unsigned s = (unsigned)__cvta_generic_to_shared(p);
    asm volatile("ldmatrix.sync.aligned.m8n8.x4.shared.b16 {%0,%1,%2,%3}, [%4];"
                 : "=r"(r[0]), "=r"(r[1]), "=r"(r[2]), "=r"(r[3]) : "r"(s));
}
__device__ __forceinline__ void ldsm4t(unsigned* r, const void* p) {
    unsigned s = (unsigned)__cvta_generic_to_shared(p);
    asm volatile("ldmatrix.sync.aligned.m8n8.x4.trans.shared.b16 {%0,%1,%2,%3}, [%4];"
                 : "=r"(r[0]), "=r"(r[1]), "=r"(r[2]), "=r"(r[3]) : "r"(s));
}

__global__ void __launch_bounds__(256) k_gemm(float* __restrict__ out) {
    extern __shared__ __nv_bfloat16 sh[];
    __nv_bfloat16* sAh = sh;
    __nv_bfloat16* sAl = sh + 2 * A_BUF;
    __nv_bfloat16* sBh = sh + 4 * A_BUF;
    __nv_bfloat16* sBl = sh + 4 * A_BUF + 2 * B_BUF;

    int tid  = threadIdx.x;
    int wid  = tid >> 5;
    int lane = tid & 31;
    int wm   = wid >> 2;
    int wn   = wid & 3;
    int m0   = blockIdx.x * 128;
    int n0   = blockIdx.y * 128;

    float acc[4][4][4];
#pragma unroll
    for (int mi = 0; mi < 4; mi++)
#pragma unroll
        for (int nj = 0; nj < 4; nj++)
#pragma unroll
            for (int q = 0; q < 4; q++) acc[mi][nj][q] = 0.f;

    auto load_stage = [&](int kb, int buf) {
#pragma unroll
        for (int q = 0; q < 2; q++) {
            int cc = tid + q * 256;
            int row = cc >> 2, seg = (cc & 3) * 8;
            size_t go = (size_t)(m0 + row) * NK + kb * 32 + seg;
            int so = buf * A_BUF + row * ASTRIDE + seg;
            cp16(sAh + so, g_Ahi + go);
            cp16(sAl + so, g_Alo + go);
        }
#pragma unroll
        for (int q = 0; q < 2; q++) {
            int cc = tid + q * 256;
            int row = cc >> 4, seg = (cc & 15) * 8;
            size_t go = (size_t)(kb * 32 + row) * ND + n0 + seg;
            int so = buf * B_BUF + row * BSTRIDE + seg;
            cp16(sBh + so, g_Bhi + go);
            cp16(sBl + so, g_Blo + go);
        }
    };

    load_stage(0, 0);
    cp_commit();

    int aRow = lane & 15, aCol = (lane >> 4) * 8;
    int bRow = lane & 15, bCol = (lane >> 4) * 8;
    int buf = 0;

    for (int kb = 0; kb < 32; kb++) {
        if (kb + 1 < 32) { load_stage(kb + 1, buf ^ 1); cp_commit(); cp_wait<1>(); }
        else             { cp_wait<0>(); }
        __syncthreads();

        const __nv_bfloat16* pAh = sAh + buf * A_BUF;
        const __nv_bfloat16* pAl = sAl + buf * A_BUF;
        const __nv_bfloat16* pBh = sBh + buf * B_BUF;
        const __nv_bfloat16* pBl = sBl + buf * B_BUF;

#pragma unroll
        for (int step = 0; step < 2; step++) {
            int k0 = step * 16;
            unsigned ah[4][4], al[4][4], bh[2][4], bl[2][4];
#pragma unroll
            for (int mi = 0; mi < 4; mi++) {
                int m = wm * 64 + mi * 16 + aRow;
                ldsm4(ah[mi], pAh + m * ASTRIDE + k0 + aCol);
                ldsm4(al[mi], pAl + m * ASTRIDE + k0 + aCol);
            }
#pragma unroll
            for (int ng = 0; ng < 2; ng++) {
                int n = wn * 32 + ng * 16 + bCol;
                ldsm4t(bh[ng], pBh + (k0 + bRow) * BSTRIDE + n);
                ldsm4t(bl[ng], pBl + (k0 + bRow) * BSTRIDE + n);
            }
#pragma unroll
            for (int mi = 0; mi < 4; mi++)
#pragma unroll
                for (int ng = 0; ng < 2; ng++)
#pragma unroll
                    for (int hf = 0; hf < 2; hf++) {
                        int nj = ng * 2 + hf;
                        unsigned bhf[2] = {bh[ng][hf * 2], bh[ng][hf * 2 + 1]};
                        unsigned blf[2] = {bl[ng][hf * 2], bl[ng][hf * 2 + 1]};
                        mma_bf16(acc[mi][nj], ah[mi], bhf);
                        mma_bf16(acc[mi][nj], ah[mi], blf);
                        mma_bf16(acc[mi][nj], al[mi], bhf);
                    }
        }
        __syncthreads();
        buf ^= 1;
    }

    int r = lane >> 2, cl = lane & 3;
#pragma unroll
    for (int mi = 0; mi < 4; mi++) {
#pragma unroll
        for (int nj = 0; nj < 4; nj++) {
            int row = m0 + wm * 64 + mi * 16 + r;
            int col = n0 + wn * 32 + nj * 8 + cl * 2;
            *(float2*)(out + (size_t)row * ND + col)       = make_float2(acc[mi][nj][0], acc[mi][nj][1]);
            *(float2*)(out + (size_t)(row + 8) * ND + col) = make_float2(acc[mi][nj][2], acc[mi][nj][3]);
        }
    }
}

// ---------------- stage 4b: bias + LayerNorm (in-place over out) ----------------
__global__ void __launch_bounds__(256) k_ln(const float* __restrict__ bc,
                                            const float* __restrict__ gamma,
                                            const float* __restrict__ beta,
                                            float* __restrict__ out) {
    __shared__ float sb[ND], sg[ND], sbe[ND];
    int tid = threadIdx.x;
#pragma unroll
    for (int q = 0; q < 2; q++) {
        int i = tid + q * 256;
        sb[i] = bc[i]; sg[i] = gamma[i]; sbe[i] = beta[i];
    }
    __syncthreads();

    int lane = tid & 31;
    int wrp  = tid >> 5;
    int row  = blockIdx.x * 8 + wrp;

    float* rp = out + (size_t)row * ND;
    float v[16];
    float s = 0.f, sq = 0.f;
#pragma unroll
    for (int q = 0; q < 4; q++) {
        int c = lane * 4 + q * 128;
        float4 x = *(const float4*)(rp + c);
        float4 bb = *(const float4*)(sb + c);
        v[q * 4 + 0] = x.x + bb.x;
        v[q * 4 + 1] = x.y + bb.y;
        v[q * 4 + 2] = x.z + bb.z;
        v[q * 4 + 3] = x.w + bb.w;
#pragma unroll
        for (int j = 0; j < 4; j++) {
            s  += v[q * 4 + j];
            sq += v[q * 4 + j] * v[q * 4 + j];
        }
    }
#pragma unroll
    for (int off = 16; off > 0; off >>= 1) {
        s  += __shfl_xor_sync(0xffffffffu, s, off);
        sq += __shfl_xor_sync(0xffffffffu, sq, off);
    }
    float mu  = s * (1.0f / 512.0f);
    float var = sq * (1.0f / 512.0f) - mu * mu;
    float rstd = rsqrtf(var + 1e-5f);
#pragma unroll
    for (int q = 0; q < 4; q++) {
        int c = lane * 4 + q * 128;
        float4 gg = *(const float4*)(sg + c);
        float4 be = *(const float4*)(sbe + c);
        float4 o;
        o.x = (v[q * 4 + 0] - mu) * rstd * gg.x + be.x;
        o.y = (v[q * 4 + 1] - mu) * rstd * gg.y + be.y;
        o.z = (v[q * 4 + 2] - mu) * rstd * gg.z + be.z;
        o.w = (v[q * 4 + 3] - mu) * rstd * gg.w + be.w;
        *(float4*)(rp + c) = o;
    }
}

// ---------------- launch ----------------
extern "C" void kernel_launch(void* const* d_in, const int* in_sizes, int n_in,
                              void* d_out, int out_size) {
    const float* outp  = (const float*)d_in[0];
    const float* attn  = (const float*)d_in[1];
    const float* oeh   = (const float*)d_in[2];
    const void*  ei    = d_in[3];
    const float* Wg    = (const float*)d_in[6];
    const float* bg    = (const float*)d_in[7];
    const float* Wl    = (const float*)d_in[8];
    const float* bl    = (const float*)d_in[9];
    const float* Wch   = (const float*)d_in[10];
    const float* bch   = (const float*)d_in[11];
    const float* Wc    = (const float*)d_in[12];
    const float* bc    = (const float*)d_in[13];
    const float* gamma = (const float*)d_in[14];
    const float* beta  = (const float*)d_in[15];
    float* out = (float*)d_out;

    int cheb_smem = 3 * NN * TST * 4;   // 208896 B
    cudaFuncSetAttribute(k_cheb, cudaFuncAttributeMaxDynamicSharedMemorySize, cheb_smem);
    int gemm_smem = (4 * A_BUF + 4 * B_BUF) * 2;
    cudaFuncSetAttribute(k_gemm, cudaFuncAttributeMaxDynamicSharedMemorySize, gemm_smem);

    k_detect<<<1, 32>>>((const int*)ei);
    k_coeff<<<NG, 256>>>(attn, Wg, bg, Wl, bl);
    k_zero<<<NTOT / 256, 256>>>();
    k_degk<<<NE / 256, 256>>>(ei);
    k_scan<<<1, 512>>>();
    k_scatter<<<NE / 256, 256>>>(ei);
    k_prepA<<<NTOT * (ND / 4) / 256, 256>>>(outp);
    k_prepW<<<(NK * ND / 4) / 256, 256>>>(Wc);
    k_prepWch<<<16, 256>>>(Wch);
    k_cheb<<<NG, 512, cheb_smem>>>(oeh, bch);
    dim3 gg2(128, 4);
    k_gemm<<<gg2, 256, gemm_smem>>>(out);
    k_ln<<<NTOT / 8, 256>>>(bc, gamma, beta, out);
}

// round 10
// speedup vs baseline: 1.9939x; 1.0966x over previous
#include <cuda_runtime.h>
#include <cuda_bf16.h>
#include <cuda_fp16.h>

// Problem constants
#define NB   64
#define NN   256
#define NH   8
#define NDH  64
#define ND   512
#define NK   1024       // 2*D concat width
#define NTOT 16384      // B*N
#define NE   262144     // TOTAL*DEG
#define NG   512        // H*B graphs
#define TST  68         // T-buffer row stride (floats)

// ---------------- device scratch ----------------
__device__ int            g_is64;
__device__ float          g_coeff[NG * 4];
__device__ float          g_dinv[NTOT];
__device__ int            g_deg[NTOT];
__device__ int            g_off[NTOT + 1];
__device__ int            g_cur[NTOT];
__device__ int2           g_epack[NE];
// fp16 hi/lo A = [outp | cheb_filtered] rows (n,b)-order; W_cat fp16 [K=1024][N=512]
__device__ __half         g_Ahi[(size_t)NTOT * NK];
__device__ __half         g_Alo[(size_t)NTOT * NK];
__device__ __half         g_Bh [(size_t)NK * ND];
// W_cheb in mma-fragment-linear order (bf16 3x, used by k_cheb)
__device__ uint2          g_Wfh[4 * 4 * 8 * 32];
__device__ uint2          g_Wfl[4 * 4 * 8 * 32];

// bf16 hi/lo pack (k_cheb internal A-fragments)
__device__ __forceinline__ void cvt_hilo(float x, float y, unsigned& h, unsigned& l) {
    __nv_bfloat16 hx = __float2bfloat16_rn(x);
    __nv_bfloat16 hy = __float2bfloat16_rn(y);
    h = (unsigned)__bfloat16_as_ushort(hx) | ((unsigned)__bfloat16_as_ushort(hy) << 16);
    __nv_bfloat16 lx = __float2bfloat16_rn(x - __bfloat162float(hx));
    __nv_bfloat16 ly = __float2bfloat16_rn(y - __bfloat162float(hy));
    l = (unsigned)__bfloat16_as_ushort(lx) | ((unsigned)__bfloat16_as_ushort(ly) << 16);
}

// fp16 hi/lo pack (GEMM A operand)
__device__ __forceinline__ void cvt_hilo_h(float x, float y, unsigned& h, unsigned& l) {
    __half hx = __float2half_rn(x);
    __half hy = __float2half_rn(y);
    h = (unsigned)__half_as_ushort(hx) | ((unsigned)__half_as_ushort(hy) << 16);
    __half lx = __float2half_rn(x - __half2float(hx));
    __half ly = __float2half_rn(y - __half2float(hy));
    l = (unsigned)__half_as_ushort(lx) | ((unsigned)__half_as_ushort(ly) << 16);
}

// ---------------- edge dtype detection ----------------
__global__ void k_detect(const int* p) {
    if (blockIdx.x == 0 && threadIdx.x == 0) {
        int ok64 = 1;
        for (int q = 1; q < 64; q += 2)
            if (p[q] != 0) ok64 = 0;
        g_is64 = ok64;
    }
}

__device__ __forceinline__ void load_edge(const void* ei, int e, int& s, int& d) {
    if (g_is64) {
        const long long* p = (const long long*)ei;
        s = (int)p[e];
        d = (int)p[NE + e];
    } else {
        const int* p = (const int*)ei;
        s = p[e];
        d = p[NE + e];
    }
}

// ---------------- stage 1: GCN coeff per graph ----------------
__global__ void __launch_bounds__(256) k_coeff(const float* __restrict__ attn,
                                               const float* __restrict__ Wg,
                                               const float* __restrict__ bg,
                                               const float* __restrict__ Wl,
                                               const float* __restrict__ bl) {
    int g = blockIdx.x;
    int h = g >> 6;
    int b = g & 63;
    const float* A = attn + ((size_t)b * NH + h) * (NN * NN);
    int j = threadIdx.x;

    __shared__ float dsm[NN];
    __shared__ float red[4];

    float cs = 0.f;
#pragma unroll 16
    for (int i = 0; i < NN; i++) cs += A[i * NN + j];
    float deg = cs + 1.0f;
    float dv = (deg > 0.f) ? rsqrtf(deg) : 0.f;
    dsm[j] = dv;
    if (j < 4) red[j] = 0.f;
    __syncthreads();

    float t = 0.f;
#pragma unroll 16
    for (int i = 0; i < NN; i++) t += dsm[i] * A[i * NN + j];
    float sj = (t + dv) * dv;

    float w_row[4], v[4];
#pragma unroll
    for (int c = 0; c < 4; c++)
        w_row[c] = Wg[c] + Wg[4 + c] + Wg[8 + c] + Wg[12 + c];
#pragma unroll
    for (int c = 0; c < 4; c++)
        v[c] = tanhf(sj * w_row[c] + bg[c]);

#pragma unroll
    for (int c = 0; c < 4; c++) {
#pragma unroll
        for (int off = 16; off > 0; off >>= 1)
            v[c] += __shfl_xor_sync(0xffffffffu, v[c], off);
    }
    if ((j & 31) == 0) {
#pragma unroll
        for (int c = 0; c < 4; c++) atomicAdd(&red[c], v[c]);
    }
    __syncthreads();

    if (j == 0) {
        float gap[4];
#pragma unroll
        for (int c = 0; c < 4; c++) gap[c] = red[c] * (1.0f / 256.0f);
#pragma unroll
        for (int c2 = 0; c2 < 4; c2++) {
            float cc = bl[c2];
#pragma unroll
            for (int c = 0; c < 4; c++) cc += gap[c] * Wl[c * 4 + c2];
            g_coeff[g * 4 + c2] = cc;
        }
    }
}

// ---------------- stage 2: edge CSR build ----------------
__global__ void k_zero() {
    int i = blockIdx.x * blockDim.x + threadIdx.x;
    if (i < NTOT) { g_deg[i] = 0; g_cur[i] = 0; }
}

__global__ void k_degk(const void* ei) {
    int e = blockIdx.x * blockDim.x + threadIdx.x;
    if (e < NE) {
        int s, d;
        load_edge(ei, e, s, d);
        atomicAdd(&g_deg[d], 1);
    }
}

__global__ void __launch_bounds__(512) k_scan() {
    __shared__ int sc[512];
    int t = threadIdx.x;
    int base = t * 32;
    int sum = 0;
    for (int i = 0; i < 32; i++) {
        int d = g_deg[base + i];
        g_dinv[base + i] = (d > 0) ? rsqrtf((float)d) : 0.f;
        sum += d;
    }
    sc[t] = sum;
    __syncthreads();
    for (int off = 1; off < 512; off <<= 1) {
        int v = sc[t];
        int u = (t >= off) ? sc[t - off] : 0;
        __syncthreads();
        sc[t] = v + u;
        __syncthreads();
    }
    int run = sc[t] - sum;
    for (int i = 0; i < 32; i++) {
        g_off[base + i] = run;
        run += g_deg[base + i];
    }
    if (t == 511) g_off[NTOT] = sc[511];
}

__global__ void k_scatter(const void* ei) {
    int e = blockIdx.x * blockDim.x + threadIdx.x;
    if (e < NE) {
        int s, d;
        load_edge(ei, e, s, d);
        float nm = -(g_dinv[s] * g_dinv[d]);
        int pos = g_off[d] + atomicAdd(&g_cur[d], 1);
        g_epack[pos] = make_int2(s & (NN - 1), __float_as_int(nm));
    }
}

// ---------------- prep: fp32 -> fp16 hi/lo ----------------
__global__ void __launch_bounds__(256) k_prepA(const float* __restrict__ outp) {
    int idx = blockIdx.x * 256 + threadIdx.x;
    int row = idx >> 7;
    int c4  = (idx & 127) * 4;
    float4 x = *(const float4*)(outp + (size_t)row * ND + c4);
    unsigned h01, l01, h23, l23;
    cvt_hilo_h(x.x, x.y, h01, l01);
    cvt_hilo_h(x.z, x.w, h23, l23);
    size_t o = (size_t)row * NK + c4;
    *(uint2*)(g_Ahi + o) = make_uint2(h01, h23);
    *(uint2*)(g_Alo + o) = make_uint2(l01, l23);
}

// W_cat [K=1024][N=512] -> fp16 (hi only)
__global__ void __launch_bounds__(256) k_prepW(const float* __restrict__ Wc) {
    int idx = blockIdx.x * 256 + threadIdx.x;   // one float4 per thread
    float4 x = *(const float4*)(Wc + (size_t)idx * 4);
    __half h[4] = {__float2half_rn(x.x), __float2half_rn(x.y),
                   __float2half_rn(x.z), __float2half_rn(x.w)};
    *(uint2*)(g_Bh + (size_t)idx * 4) = *(uint2*)h;
}

// W_cheb -> mma fragment-linear hi/lo (bf16)
__global__ void __launch_bounds__(256) k_prepWch(const float* __restrict__ Wch) {
    int i = blockIdx.x * 256 + threadIdx.x;
    if (i >= 4096) return;
    int lane = i & 31, nt = (i >> 5) & 7, kt = (i >> 8) & 3, k = i >> 10;
    int tt = lane & 3, gg = lane >> 2;
    int n = nt * 8 + gg;
    unsigned h[2], l[2];
#pragma unroll
    for (int reg = 0; reg < 2; reg++) {
        int kr = kt * 16 + 2 * tt + reg * 8;
        float w0 = Wch[k * 4096 + kr * 64 + n];
        float w1 = Wch[k * 4096 + (kr + 1) * 64 + n];
        cvt_hilo(w0, w1, h[reg], l[reg]);
    }
    g_Wfh[i] = make_uint2(h[0], h[1]);
    g_Wfl[i] = make_uint2(l[0], l[1]);
}

// ---------------- mma helpers ----------------
__device__ __forceinline__ void mma_bf16(float* c, const unsigned* a, const unsigned* b) {
    asm volatile(
        "mma.sync.aligned.m16n8k16.row.col.f32.bf16.bf16.f32 "
        "{%0,%1,%2,%3}, {%4,%5,%6,%7}, {%8,%9}, {%0,%1,%2,%3};"
        : "+f"(c[0]), "+f"(c[1]), "+f"(c[2]), "+f"(c[3])
        : "r"(a[0]), "r"(a[1]), "r"(a[2]), "r"(a[3]), "r"(b[0]), "r"(b[1]));
}
__device__ __forceinline__ void mma_f16(float* c, const unsigned* a, const unsigned* b) {
    asm volatile(
        "mma.sync.aligned.m16n8k16.row.col.f32.f16.f16.f32 "
        "{%0,%1,%2,%3}, {%4,%5,%6,%7}, {%8,%9}, {%0,%1,%2,%3};"
        : "+f"(c[0]), "+f"(c[1]), "+f"(c[2]), "+f"(c[3])
        : "r"(a[0]), "r"(a[1]), "r"(a[2]), "r"(a[3]), "r"(b[0]), "r"(b[1]));
}

// ---------------- stage 3: Chebyshev prop + tensor-core matmul ----------------
__global__ void __launch_bounds__(512, 1) k_cheb(const float* __restrict__ oeh,
                                                 const float* __restrict__ bch) {
    extern __shared__ float sm[];
    float* S0 = sm;
    float* S1 = sm + NN * TST;
    float* S2 = sm + 2 * NN * TST;

    int g = blockIdx.x;
    int h = g >> 6;
    int b = g & 63;
    int tid = threadIdx.x;
    int w = tid >> 5;
    int lane = tid & 31;
    int n0 = w * 16;
    int gr = lane >> 2, tt = lane & 3;

    const float* xb = oeh + (size_t)b * 131072 + (size_t)h * 64;
    for (int idx = tid; idx < NN * NDH; idx += 512) {
        int n = idx >> 6, d = idx & 63;
        S0[n * TST + d] = xb[(size_t)n * 512 + d];
    }

    float c[4];
#pragma unroll
    for (int k = 0; k < 4; k++) c[k] = g_coeff[g * 4 + k];

    float accf[8][4];
#pragma unroll
    for (int nt = 0; nt < 8; nt++)
#pragma unroll
        for (int q = 0; q < 4; q++) accf[nt][q] = 0.f;

    __syncthreads();

    auto matmul = [&](const float* T, int k) {
        float ck = c[k];
#pragma unroll
        for (int kt = 0; kt < 4; kt++) {
            int kc = kt * 16 + 2 * tt;
            float2 x0 = *(const float2*)&T[(n0 + gr) * TST + kc];
            float2 x1 = *(const float2*)&T[(n0 + gr + 8) * TST + kc];
            float2 x2 = *(const float2*)&T[(n0 + gr) * TST + kc + 8];
            float2 x3 = *(const float2*)&T[(n0 + gr + 8) * TST + kc + 8];
            unsigned ah[4], al[4];
            cvt_hilo(ck * x0.x, ck * x0.y, ah[0], al[0]);
            cvt_hilo(ck * x1.x, ck * x1.y, ah[1], al[1]);
            cvt_hilo(ck * x2.x, ck * x2.y, ah[2], al[2]);
            cvt_hilo(ck * x3.x, ck * x3.y, ah[3], al[3]);
            const uint2* WH = g_Wfh + ((k * 4 + kt) * 8) * 32 + lane;
            const uint2* WL = g_Wfl + ((k * 4 + kt) * 8) * 32 + lane;
#pragma unroll
            for (int nt = 0; nt < 8; nt++) {
                uint2 bh = WH[nt * 32];
                uint2 bl = WL[nt * 32];
                unsigned bhv[2] = {bh.x, bh.y};
                unsigned blv[2] = {bl.x, bl.y};
                mma_bf16(accf[nt], ah, bhv);
                mma_bf16(accf[nt], ah, blv);
                mma_bf16(accf[nt], al, bhv);
            }
        }
    };

    auto prop = [&](const float* Tsrc, const float* Tprev, float* Tdst, bool first) {
        for (int i = 0; i < 16; i++) {
            int n = n0 + i;
            int dn = b * NN + n;
            int eb = g_off[dn], ee = g_off[dn + 1];
            float s0a = 0.f, s1a = 0.f, s0b = 0.f, s1b = 0.f;
            int e = eb;
            for (; e + 1 < ee; e += 2) {
                int2 e0 = g_epack[e];
                int2 e1 = g_epack[e + 1];
                float w0 = __int_as_float(e0.y);
                float w1 = __int_as_float(e1.y);
                float2 t0 = *(const float2*)&Tsrc[e0.x * TST + 2 * lane];
                float2 t1 = *(const float2*)&Tsrc[e1.x * TST + 2 * lane];
                s0a += w0 * t0.x; s1a += w0 * t0.y;
                s0b += w1 * t1.x; s1b += w1 * t1.y;
            }
            if (e < ee) {
                int2 e0 = g_epack[e];
                float w0 = __int_as_float(e0.y);
                float2 t0 = *(const float2*)&Tsrc[e0.x * TST + 2 * lane];
                s0a += w0 * t0.x; s1a += w0 * t0.y;
            }
            float s0 = s0a + s0b, s1 = s1a + s1b;
            int o = n * TST + 2 * lane;
            if (first) {
                *(float2*)&Tdst[o] = make_float2(s0, s1);
            } else {
                float2 pv = *(const float2*)&Tprev[o];
                *(float2*)&Tdst[o] = make_float2(2.f * s0 - pv.x, 2.f * s1 - pv.y);
            }
        }
    };

    matmul(S0, 0);
    prop(S0, nullptr, S1, true);
    matmul(S1, 1);
    __syncthreads();
    prop(S1, S0, S2, false);
    matmul(S2, 2);
    __syncthreads();
    prop(S2, S1, S0, false);
    matmul(S0, 3);

    // epilogue: bias + fp16 hi/lo into A cols 512+
#pragma unroll
    for (int nt = 0; nt < 8; nt++) {
        int o = nt * 8 + tt * 2;
        float b0 = bch[o], b1 = bch[o + 1];
        float c0 = accf[nt][0] + b0, c1 = accf[nt][1] + b1;
        float c2 = accf[nt][2] + b0, c3 = accf[nt][3] + b1;
        unsigned h01, l01, h23, l23;
        cvt_hilo_h(c0, c1, h01, l01);
        cvt_hilo_h(c2, c3, h23, l23);
        int nA = n0 + gr;
        size_t r1 = (size_t)(nA * 64 + b) * NK + 512 + h * 64 + o;
        size_t r2 = (size_t)((nA + 8) * 64 + b) * NK + 512 + h * 64 + o;
        *(unsigned*)(g_Ahi + r1) = h01;
        *(unsigned*)(g_Alo + r1) = l01;
        *(unsigned*)(g_Ahi + r2) = h23;
        *(unsigned*)(g_Alo + r2) = l23;
    }
}

// ---------------- stage 4a: 2x-fp16 tensor-core GEMM ----------------
// out = A @ W via Ah*Bh + Al*Bh (fp16 hi/lo A, fp16 B)
#define ASTRIDE 40     // 32 + 8 pad (fp16 el)
#define BSTRIDE 136    // 128 + 8 pad
#define A_BUF   (128 * ASTRIDE)
#define B_BUF   (32 * BSTRIDE)

__device__ __forceinline__ void cp16(void* smem_dst, const void* gmem_src) {
    unsigned s = (unsigned)__cvta_generic_to_shared(smem_dst);
    asm volatile("cp.async.cg.shared.global [%0], [%1], 16;" :: "r"(s), "l"(gmem_src));
}
__device__ __forceinline__ void cp_commit() { asm volatile("cp.async.commit_group;"); }
template <int N>
__device__ __forceinline__ void cp_wait() { asm volatile("cp.async.wait_group %0;" :: "n"(N)); }

__device__ __forceinline__ void ldsm4(unsigned* r, const void* p) {
    unsigned s = (unsigned)__cvta_generic_to_shared(p);
    asm volatile("ldmatrix.sync.aligned.m8n8.x4.shared.b16 {%0,%1,%2,%3}, [%4];"
                 : "=r"(r[0]), "=r"(r[1]), "=r"(r[2]), "=r"(r[3]) : "r"(s));
}
__device__ __forceinline__ void ldsm4t(unsigned* r, const void* p) {
    unsigned s = (unsigned)__cvta_generic_to_shared(p);
    asm volatile("ldmatrix.sync.aligned.m8n8.x4.trans.shared.b16 {%0,%1,%2,%3}, [%4];"
                 : "=r"(r[0]), "=r"(r[1]), "=r"(r[2]), "=r"(r[3]) : "r"(s));
}

__global__ void __launch_bounds__(256) k_gemm(float* __restrict__ out) {
    extern __shared__ __half sh[];
    __half* sAh = sh;                     // [2][A_BUF]
    __half* sAl = sh + 2 * A_BUF;         // [2][A_BUF]
    __half* sBh = sh + 4 * A_BUF;         // [2][B_BUF]

    int tid  = threadIdx.x;
    int wid  = tid >> 5;
    int lane = tid & 31;
    int wm   = wid >> 2;
    int wn   = wid & 3;
    int m0   = blockIdx.x * 128;
    int n0   = blockIdx.y * 128;

    float acc[4][4][4];
#pragma unroll
    for (int mi = 0; mi < 4; mi++)
#pragma unroll
        for (int nj = 0; nj < 4; nj++)
#pragma unroll
            for (int q = 0; q < 4; q++) acc[mi][nj][q] = 0.f;

    auto load_stage = [&](int kb, int buf) {
#pragma unroll
        for (int q = 0; q < 2; q++) {
            int cc = tid + q * 256;
            int row = cc >> 2, seg = (cc & 3) * 8;
            size_t go = (size_t)(m0 + row) * NK + kb * 32 + seg;
            int so = buf * A_BUF + row * ASTRIDE + seg;
            cp16(sAh + so, g_Ahi + go);
            cp16(sAl + so, g_Alo + go);
        }
#pragma unroll
        for (int q = 0; q < 2; q++) {
            int cc = tid + q * 256;
            int row = cc >> 4, seg = (cc & 15) * 8;
            size_t go = (size_t)(kb * 32 + row) * ND + n0 + seg;
            int so = buf * B_BUF + row * BSTRIDE + seg;
            cp16(sBh + so, g_Bh + go);
        }
    };

    load_stage(0, 0);
    cp_commit();

    int aRow = lane & 15, aCol = (lane >> 4) * 8;
    int bRow = lane & 15, bCol = (lane >> 4) * 8;
    int buf = 0;

    for (int kb = 0; kb < 32; kb++) {
        if (kb + 1 < 32) { load_stage(kb + 1, buf ^ 1); cp_commit(); cp_wait<1>(); }
        else             { cp_wait<0>(); }
        __syncthreads();

        const __half* pAh = sAh + buf * A_BUF;
        const __half* pAl = sAl + buf * A_BUF;
        const __half* pBh = sBh + buf * B_BUF;

#pragma unroll
        for (int step = 0; step < 2; step++) {
            int k0 = step * 16;
            unsigned ah[4][4], al[4][4], bh[2][4];
#pragma unroll
            for (int mi = 0; mi < 4; mi++) {
                int m = wm * 64 + mi * 16 + aRow;
                ldsm4(ah[mi], pAh + m * ASTRIDE + k0 + aCol);
                ldsm4(al[mi], pAl + m * ASTRIDE + k0 + aCol);
            }
#pragma unroll
            for (int ng = 0; ng < 2; ng++) {
                int n = wn * 32 + ng * 16 + bCol;
                ldsm4t(bh[ng], pBh + (k0 + bRow) * BSTRIDE + n);
            }
#pragma unroll
            for (int mi = 0; mi < 4; mi++)
#pragma unroll
                for (int ng = 0; ng < 2; ng++)
#pragma unroll
                    for (int hf = 0; hf < 2; hf++) {
                        int nj = ng * 2 + hf;
                        unsigned bhf[2] = {bh[ng][hf * 2], bh[ng][hf * 2 + 1]};
                        mma_f16(acc[mi][nj], ah[mi], bhf);
                        mma_f16(acc[mi][nj], al[mi], bhf);
                    }
        }
        __syncthreads();
        buf ^= 1;
    }

    int r = lane >> 2, cl = lane & 3;
#pragma unroll
    for (int mi = 0; mi < 4; mi++) {
#pragma unroll
        for (int nj = 0; nj < 4; nj++) {
            int row = m0 + wm * 64 + mi * 16 + r;
            int col = n0 + wn * 32 + nj * 8 + cl * 2;
            *(float2*)(out + (size_t)row * ND + col)       = make_float2(acc[mi][nj][0], acc[mi][nj][1]);
            *(float2*)(out + (size_t)(row + 8) * ND + col) = make_float2(acc[mi][nj][2], acc[mi][nj][3]);
        }
    }
}

// ---------------- stage 4b: bias + LayerNorm (in-place over out) ----------------
__global__ void __launch_bounds__(256) k_ln(const float* __restrict__ bc,
                                            const float* __restrict__ gamma,
                                            const float* __restrict__ beta,
                                            float* __restrict__ out) {
    __shared__ float sbf[ND], sg[ND], sbe[ND];
    int tid = threadIdx.x;
#pragma unroll
    for (int q = 0; q < 2; q++) {
        int i = tid + q * 256;
        sbf[i] = bc[i]; sg[i] = gamma[i]; sbe[i] = beta[i];
    }
    __syncthreads();

    int lane = tid & 31;
    int wrp  = tid >> 5;
    int row  = blockIdx.x * 8 + wrp;

    float* rp = out + (size_t)row * ND;
    float v[16];
    float s = 0.f, sq = 0.f;
#pragma unroll
    for (int q = 0; q < 4; q++) {
        int c = lane * 4 + q * 128;
        float4 x = *(const float4*)(rp + c);
        float4 bb = *(const float4*)(sbf + c);
        v[q * 4 + 0] = x.x + bb.x;
        v[q * 4 + 1] = x.y + bb.y;
        v[q * 4 + 2] = x.z + bb.z;
        v[q * 4 + 3] = x.w + bb.w;
#pragma unroll
        for (int j = 0; j < 4; j++) {
            s  += v[q * 4 + j];
            sq += v[q * 4 + j] * v[q * 4 + j];
        }
    }
#pragma unroll
    for (int off = 16; off > 0; off >>= 1) {
        s  += __shfl_xor_sync(0xffffffffu, s, off);
        sq += __shfl_xor_sync(0xffffffffu, sq, off);
    }
    float mu  = s * (1.0f / 512.0f);
    float var = sq * (1.0f / 512.0f) - mu * mu;
    float rstd = rsqrtf(var + 1e-5f);
#pragma unroll
    for (int q = 0; q < 4; q++) {
        int c = lane * 4 + q * 128;
        float4 gg = *(const float4*)(sg + c);
        float4 be = *(const float4*)(sbe + c);
        float4 o;
        o.x = (v[q * 4 + 0] - mu) * rstd * gg.x + be.x;
        o.y = (v[q * 4 + 1] - mu) * rstd * gg.y + be.y;
        o.z = (v[q * 4 + 2] - mu) * rstd * gg.z + be.z;
        o.w = (v[q * 4 + 3] - mu) * rstd * gg.w + be.w;
        *(float4*)(rp + c) = o;
    }
}

// ---------------- launch ----------------
extern "C" void kernel_launch(void* const* d_in, const int* in_sizes, int n_in,
                              void* d_out, int out_size) {
    const float* outp  = (const float*)d_in[0];
    const float* attn  = (const float*)d_in[1];
    const float* oeh   = (const float*)d_in[2];
    const void*  ei    = d_in[3];
    const float* Wg    = (const float*)d_in[6];
    const float* bg    = (const float*)d_in[7];
    const float* Wl    = (const float*)d_in[8];
    const float* bl    = (const float*)d_in[9];
    const float* Wch   = (const float*)d_in[10];
    const float* bch   = (const float*)d_in[11];
    const float* Wc    = (const float*)d_in[12];
    const float* bc    = (const float*)d_in[13];
    const float* gamma = (const float*)d_in[14];
    const float* beta  = (const float*)d_in[15];
    float* out = (float*)d_out;

    int cheb_smem = 3 * NN * TST * 4;
    cudaFuncSetAttribute(k_cheb, cudaFuncAttributeMaxDynamicSharedMemorySize, cheb_smem);
    int gemm_smem = (4 * A_BUF + 2 * B_BUF) * 2;   // bytes (fp16)
    cudaFuncSetAttribute(k_gemm, cudaFuncAttributeMaxDynamicSharedMemorySize, gemm_smem);

    k_detect<<<1, 32>>>((const int*)ei);
    k_coeff<<<NG, 256>>>(attn, Wg, bg, Wl, bl);
    k_zero<<<NTOT / 256, 256>>>();
    k_degk<<<NE / 256, 256>>>(ei);
    k_scan<<<1, 512>>>();
    k_scatter<<<NE / 256, 256>>>(ei);
    k_prepA<<<NTOT * (ND / 4) / 256, 256>>>(outp);
    k_prepW<<<(NK * ND / 4) / 256, 256>>>(Wc);
    k_prepWch<<<16, 256>>>(Wch);
    k_cheb<<<NG, 512, cheb_smem>>>(oeh, bch);
    dim3 gg2(128, 4);
    k_gemm<<<gg2, 256, gemm_smem>>>(out);
    k_ln<<<NTOT / 8, 256>>>(bc, gamma, beta, out);
}

// round 14
// speedup vs baseline: 2.0607x; 1.0335x over previous
#include <cuda_runtime.h>
#include <cuda_bf16.h>
#include <cuda_fp16.h>

// Problem constants
#define NB   64
#define NN   256
#define NH   8
#define NDH  64
#define ND   512
#define NK   1024       // 2*D concat width
#define NTOT 16384      // B*N
#define NE   262144     // TOTAL*DEG
#define NG   512        // H*B graphs
#define TST  68         // T-buffer row stride (floats)

// ---------------- device scratch ----------------
__device__ int            g_is64;
__device__ float          g_coeff[NG * 4];
__device__ float          g_dinv[NTOT];
__device__ int            g_deg[NTOT];
__device__ int            g_off[NTOT + 1];
__device__ int            g_cur[NTOT];
__device__ int2           g_epack[NE];
// fp16 hi/lo A = [outp | cheb_filtered] rows (n,b)-order; W_cat fp16 [K=1024][N=512]
__device__ __half         g_Ahi[(size_t)NTOT * NK];
__device__ __half         g_Alo[(size_t)NTOT * NK];
__device__ __half         g_Bh [(size_t)NK * ND];
// W_cheb in mma-fragment-linear order (fp16, single precision level)
__device__ uint2          g_Wf[4 * 4 * 8 * 32];

// fp16 hi/lo pack
__device__ __forceinline__ void cvt_hilo_h(float x, float y, unsigned& h, unsigned& l) {
    __half hx = __float2half_rn(x);
    __half hy = __float2half_rn(y);
    h = (unsigned)__half_as_ushort(hx) | ((unsigned)__half_as_ushort(hy) << 16);
    __half lx = __float2half_rn(x - __half2float(hx));
    __half ly = __float2half_rn(y - __half2float(hy));
    l = (unsigned)__half_as_ushort(lx) | ((unsigned)__half_as_ushort(ly) << 16);
}
__device__ __forceinline__ unsigned pack_h2(float x, float y) {
    __half hx = __float2half_rn(x);
    __half hy = __float2half_rn(y);
    return (unsigned)__half_as_ushort(hx) | ((unsigned)__half_as_ushort(hy) << 16);
}

// ---------------- edge dtype detection ----------------
__global__ void k_detect(const int* p) {
    if (blockIdx.x == 0 && threadIdx.x == 0) {
        int ok64 = 1;
        for (int q = 1; q < 64; q += 2)
            if (p[q] != 0) ok64 = 0;
        g_is64 = ok64;
    }
}

__device__ __forceinline__ void load_edge(const void* ei, int e, int& s, int& d) {
    if (g_is64) {
        const long long* p = (const long long*)ei;
        s = (int)p[e];
        d = (int)p[NE + e];
    } else {
        const int* p = (const int*)ei;
        s = p[e];
        d = p[NE + e];
    }
}

// ---------------- stage 1: GCN coeff per graph ----------------
__global__ void __launch_bounds__(256) k_coeff(const float* __restrict__ attn,
                                               const float* __restrict__ Wg,
                                               const float* __restrict__ bg,
                                               const float* __restrict__ Wl,
                                               const float* __restrict__ bl) {
    int g = blockIdx.x;
    int h = g >> 6;
    int b = g & 63;
    const float* A = attn + ((size_t)b * NH + h) * (NN * NN);
    int j = threadIdx.x;

    __shared__ float dsm[NN];
    __shared__ float red[4];

    float cs = 0.f;
#pragma unroll 16
    for (int i = 0; i < NN; i++) cs += A[i * NN + j];
    float deg = cs + 1.0f;
    float dv = (deg > 0.f) ? rsqrtf(deg) : 0.f;
    dsm[j] = dv;
    if (j < 4) red[j] = 0.f;
    __syncthreads();

    float t = 0.f;
#pragma unroll 16
    for (int i = 0; i < NN; i++) t += dsm[i] * A[i * NN + j];
    float sj = (t + dv) * dv;

    float w_row[4], v[4];
#pragma unroll
    for (int c = 0; c < 4; c++)
        w_row[c] = Wg[c] + Wg[4 + c] + Wg[8 + c] + Wg[12 + c];
#pragma unroll
    for (int c = 0; c < 4; c++)
        v[c] = tanhf(sj * w_row[c] + bg[c]);

#pragma unroll
    for (int c = 0; c < 4; c++) {
#pragma unroll
        for (int off = 16; off > 0; off >>= 1)
            v[c] += __shfl_xor_sync(0xffffffffu, v[c], off);
    }
    if ((j & 31) == 0) {
#pragma unroll
        for (int c = 0; c < 4; c++) atomicAdd(&red[c], v[c]);
    }
    __syncthreads();

    if (j == 0) {
        float gap[4];
#pragma unroll
        for (int c = 0; c < 4; c++) gap[c] = red[c] * (1.0f / 256.0f);
#pragma unroll
        for (int c2 = 0; c2 < 4; c2++) {
            float cc = bl[c2];
#pragma unroll
            for (int c = 0; c < 4; c++) cc += gap[c] * Wl[c * 4 + c2];
            g_coeff[g * 4 + c2] = cc;
        }
    }
}

// ---------------- stage 2: edge CSR build ----------------
__global__ void k_degk(const void* ei) {
    int e = blockIdx.x * blockDim.x + threadIdx.x;
    if (e < NE) {
        int s, d;
        load_edge(ei, e, s, d);
        atomicAdd(&g_deg[d], 1);
    }
}

__global__ void __launch_bounds__(512) k_scan() {
    __shared__ int sc[512];
    int t = threadIdx.x;
    int base = t * 32;
    int sum = 0;
    for (int i = 0; i < 32; i++) {
        int d = g_deg[base + i];
        g_dinv[base + i] = (d > 0) ? rsqrtf((float)d) : 0.f;
        sum += d;
    }
    sc[t] = sum;
    __syncthreads();
    for (int off = 1; off < 512; off <<= 1) {
        int v = sc[t];
        int u = (t >= off) ? sc[t - off] : 0;
        __syncthreads();
        sc[t] = v + u;
        __syncthreads();
    }
    int run = sc[t] - sum;
    for (int i = 0; i < 32; i++) {
        g_off[base + i] = run;
        run += g_deg[base + i];
    }
    if (t == 511) g_off[NTOT] = sc[511];
}

__global__ void k_scatter(const void* ei) {
    int e = blockIdx.x * blockDim.x + threadIdx.x;
    if (e < NE) {
        int s, d;
        load_edge(ei, e, s, d);
        float nm = -(g_dinv[s] * g_dinv[d]);
        int pos = g_off[d] + atomicAdd(&g_cur[d], 1);
        g_epack[pos] = make_int2(s & (NN - 1), __float_as_int(nm));
    }
}

// ---------------- fused prep kernel ----------------
// blocks [0,8192)      : A cols 0..511 from outp -> fp16 hi/lo
// blocks [8192,8704)   : W_cat -> fp16
// blocks [8704,8720)   : W_cheb -> mma fragment-linear fp16
// blocks [8720,8784)   : zero deg/cur counters
__global__ void __launch_bounds__(256) k_prep(const float* __restrict__ outp,
                                              const float* __restrict__ Wc,
                                              const float* __restrict__ Wch) {
    int blk = blockIdx.x;
    int tid = threadIdx.x;
    if (blk < 8192) {
        int idx = blk * 256 + tid;
        int row = idx >> 7;
        int c4  = (idx & 127) * 4;
        float4 x = *(const float4*)(outp + (size_t)row * ND + c4);
        unsigned h01, l01, h23, l23;
        cvt_hilo_h(x.x, x.y, h01, l01);
        cvt_hilo_h(x.z, x.w, h23, l23);
        size_t o = (size_t)row * NK + c4;
        *(uint2*)(g_Ahi + o) = make_uint2(h01, h23);
        *(uint2*)(g_Alo + o) = make_uint2(l01, l23);
    } else if (blk < 8704) {
        int idx = (blk - 8192) * 256 + tid;
        float4 x = *(const float4*)(Wc + (size_t)idx * 4);
        *(uint2*)(g_Bh + (size_t)idx * 4) = make_uint2(pack_h2(x.x, x.y), pack_h2(x.z, x.w));
    } else if (blk < 8720) {
        int i = (blk - 8704) * 256 + tid;
        int lane = i & 31, nt = (i >> 5) & 7, kt = (i >> 8) & 3, k = i >> 10;
        int tt = lane & 3, gg = lane >> 2;
        int n = nt * 8 + gg;
        unsigned h[2];
#pragma unroll
        for (int reg = 0; reg < 2; reg++) {
            int kr = kt * 16 + 2 * tt + reg * 8;
            h[reg] = pack_h2(Wch[k * 4096 + kr * 64 + n], Wch[k * 4096 + (kr + 1) * 64 + n]);
        }
        g_Wf[i] = make_uint2(h[0], h[1]);
    } else {
        int i = (blk - 8720) * 256 + tid;
        g_deg[i] = 0;
        g_cur[i] = 0;
    }
}

// ---------------- mma helper ----------------
__device__ __forceinline__ void mma_f16(float* c, const unsigned* a, const unsigned* b) {
    asm volatile(
        "mma.sync.aligned.m16n8k16.row.col.f32.f16.f16.f32 "
        "{%0,%1,%2,%3}, {%4,%5,%6,%7}, {%8,%9}, {%0,%1,%2,%3};"
        : "+f"(c[0]), "+f"(c[1]), "+f"(c[2]), "+f"(c[3])
        : "r"(a[0]), "r"(a[1]), "r"(a[2]), "r"(a[3]), "r"(b[0]), "r"(b[1]));
}

// ---------------- stage 3: Chebyshev prop + tensor-core matmul (2x fp16) ----------------
__global__ void __launch_bounds__(512, 1) k_cheb(const float* __restrict__ oeh,
                                                 const float* __restrict__ bch) {
    extern __shared__ float sm[];
    float* S0 = sm;
    float* S1 = sm + NN * TST;
    float* S2 = sm + 2 * NN * TST;

    int g = blockIdx.x;
    int h = g >> 6;
    int b = g & 63;
    int tid = threadIdx.x;
    int w = tid >> 5;
    int lane = tid & 31;
    int n0 = w * 16;
    int gr = lane >> 2, tt = lane & 3;

    const float* xb = oeh + (size_t)b * 131072 + (size_t)h * 64;
    for (int idx = tid; idx < NN * NDH; idx += 512) {
        int n = idx >> 6, d = idx & 63;
        S0[n * TST + d] = xb[(size_t)n * 512 + d];
    }

    float c[4];
#pragma unroll
    for (int k = 0; k < 4; k++) c[k] = g_coeff[g * 4 + k];

    float accf[8][4];
#pragma unroll
    for (int nt = 0; nt < 8; nt++)
#pragma unroll
        for (int q = 0; q < 4; q++) accf[nt][q] = 0.f;

    __syncthreads();

    auto matmul = [&](const float* T, int k) {
        float ck = c[k];
#pragma unroll
        for (int kt = 0; kt < 4; kt++) {
            int kc = kt * 16 + 2 * tt;
            float2 x0 = *(const float2*)&T[(n0 + gr) * TST + kc];
            float2 x1 = *(const float2*)&T[(n0 + gr + 8) * TST + kc];
            float2 x2 = *(const float2*)&T[(n0 + gr) * TST + kc + 8];
            float2 x3 = *(const float2*)&T[(n0 + gr + 8) * TST + kc + 8];
            unsigned ah[4], al[4];
            cvt_hilo_h(ck * x0.x, ck * x0.y, ah[0], al[0]);
            cvt_hilo_h(ck * x1.x, ck * x1.y, ah[1], al[1]);
            cvt_hilo_h(ck * x2.x, ck * x2.y, ah[2], al[2]);
            cvt_hilo_h(ck * x3.x, ck * x3.y, ah[3], al[3]);
            const uint2* WF = g_Wf + ((k * 4 + kt) * 8) * 32 + lane;
#pragma unroll
            for (int nt = 0; nt < 8; nt++) {
                uint2 bh = WF[nt * 32];
                unsigned bhv[2] = {bh.x, bh.y};
                mma_f16(accf[nt], ah, bhv);
                mma_f16(accf[nt], al, bhv);
            }
        }
    };

    auto prop = [&](const float* Tsrc, const float* Tprev, float* Tdst, bool first) {
        for (int i = 0; i < 16; i++) {
            int n = n0 + i;
            int dn = b * NN + n;
            int eb = g_off[dn], ee = g_off[dn + 1];
            float s0a = 0.f, s1a = 0.f, s0b = 0.f, s1b = 0.f;
            int e = eb;
            for (; e + 1 < ee; e += 2) {
                int2 e0 = g_epack[e];
                int2 e1 = g_epack[e + 1];
                float w0 = __int_as_float(e0.y);
                float w1 = __int_as_float(e1.y);
                float2 t0 = *(const float2*)&Tsrc[e0.x * TST + 2 * lane];
                float2 t1 = *(const float2*)&Tsrc[e1.x * TST + 2 * lane];
                s0a += w0 * t0.x; s1a += w0 * t0.y;
                s0b += w1 * t1.x; s1b += w1 * t1.y;
            }
            if (e < ee) {
                int2 e0 = g_epack[e];
                float w0 = __int_as_float(e0.y);
                float2 t0 = *(const float2*)&Tsrc[e0.x * TST + 2 * lane];
                s0a += w0 * t0.x; s1a += w0 * t0.y;
            }
            float s0 = s0a + s0b, s1 = s1a + s1b;
            int o = n * TST + 2 * lane;
            if (first) {
                *(float2*)&Tdst[o] = make_float2(s0, s1);
            } else {
                float2 pv = *(const float2*)&Tprev[o];
                *(float2*)&Tdst[o] = make_float2(2.f * s0 - pv.x, 2.f * s1 - pv.y);
            }
        }
    };

    matmul(S0, 0);
    prop(S0, nullptr, S1, true);
    matmul(S1, 1);
    __syncthreads();
    prop(S1, S0, S2, false);
    matmul(S2, 2);
    __syncthreads();
    prop(S2, S1, S0, false);
    matmul(S0, 3);

    // epilogue: bias + fp16 hi/lo into A cols 512+
#pragma unroll
    for (int nt = 0; nt < 8; nt++) {
        int o = nt * 8 + tt * 2;
        float b0 = bch[o], b1 = bch[o + 1];
        float c0 = accf[nt][0] + b0, c1 = accf[nt][1] + b1;
        float c2 = accf[nt][2] + b0, c3 = accf[nt][3] + b1;
        unsigned h01, l01, h23, l23;
        cvt_hilo_h(c0, c1, h01, l01);
        cvt_hilo_h(c2, c3, h23, l23);
        int nA = n0 + gr;
        size_t r1 = (size_t)(nA * 64 + b) * NK + 512 + h * 64 + o;
        size_t r2 = (size_t)((nA + 8) * 64 + b) * NK + 512 + h * 64 + o;
        *(unsigned*)(g_Ahi + r1) = h01;
        *(unsigned*)(g_Alo + r1) = l01;
        *(unsigned*)(g_Ahi + r2) = h23;
        *(unsigned*)(g_Alo + r2) = l23;
    }
}

// ---------------- stage 4a: 2x-fp16 tensor-core GEMM ----------------
#define ASTRIDE 40     // 32 + 8 pad (fp16 el)
#define BSTRIDE 136    // 128 + 8 pad
#define A_BUF   (128 * ASTRIDE)
#define B_BUF   (32 * BSTRIDE)

__device__ __forceinline__ void cp16(void* smem_dst, const void* gmem_src) {
    unsigned s = (unsigned)__cvta_generic_to_shared(smem_dst);
    asm volatile("cp.async.cg.shared.global [%0], [%1], 16;" :: "r"(s), "l"(gmem_src));
}
__device__ __forceinline__ void cp_commit() { asm volatile("cp.async.commit_group;"); }
template <int N>
__device__ __forceinline__ void cp_wait() { asm volatile("cp.async.wait_group %0;" :: "n"(N)); }

__device__ __forceinline__ void ldsm4(unsigned* r, const void* p) {
    unsigned s = (unsigned)__cvta_generic_to_shared(p);
    asm volatile("ldmatrix.sync.aligned.m8n8.x4.shared.b16 {%0,%1,%2,%3}, [%4];"
                 : "=r"(r[0]), "=r"(r[1]), "=r"(r[2]), "=r"(r[3]) : "r"(s));
}
__device__ __forceinline__ void ldsm4t(unsigned* r, const void* p) {
    unsigned s = (unsigned)__cvta_generic_to_shared(p);
    asm volatile("ldmatrix.sync.aligned.m8n8.x4.trans.shared.b16 {%0,%1,%2,%3}, [%4];"
                 : "=r"(r[0]), "=r"(r[1]), "=r"(r[2]), "=r"(r[3]) : "r"(s));
}

__global__ void __launch_bounds__(256) k_gemm(float* __restrict__ out) {
    extern __shared__ __half sh[];
    __half* sAh = sh;
    __half* sAl = sh + 2 * A_BUF;
    __half* sBh = sh + 4 * A_BUF;

    int tid  = threadIdx.x;
    int wid  = tid >> 5;
    int lane = tid & 31;
    int wm   = wid >> 2;
    int wn   = wid & 3;
    int m0   = blockIdx.x * 128;
    int n0   = blockIdx.y * 128;

    float acc[4][4][4];
#pragma unroll
    for (int mi = 0; mi < 4; mi++)
#pragma unroll
        for (int nj = 0; nj < 4; nj++)
#pragma unroll
            for (int q = 0; q < 4; q++) acc[mi][nj][q] = 0.f;

    auto load_stage = [&](int kb, int buf) {
#pragma unroll
        for (int q = 0; q < 2; q++) {
            int cc = tid + q * 256;
            int row = cc >> 2, seg = (cc & 3) * 8;
            size_t go = (size_t)(m0 + row) * NK + kb * 32 + seg;
            int so = buf * A_BUF + row * ASTRIDE + seg;
            cp16(sAh + so, g_Ahi + go);
            cp16(sAl + so, g_Alo + go);
        }
#pragma unroll
        for (int q = 0; q < 2; q++) {
            int cc = tid + q * 256;
            int row = cc >> 4, seg = (cc & 15) * 8;
            size_t go = (size_t)(kb * 32 + row) * ND + n0 + seg;
            int so = buf * B_BUF + row * BSTRIDE + seg;
            cp16(sBh + so, g_Bh + go);
        }
    };

    load_stage(0, 0);
    cp_commit();

    int aRow = lane & 15, aCol = (lane >> 4) * 8;
    int bRow = lane & 15, bCol = (lane >> 4) * 8;
    int buf = 0;

    for (int kb = 0; kb < 32; kb++) {
        if (kb + 1 < 32) { load_stage(kb + 1, buf ^ 1); cp_commit(); cp_wait<1>(); }
        else             { cp_wait<0>(); }
        __syncthreads();

        const __half* pAh = sAh + buf * A_BUF;
        const __half* pAl = sAl + buf * A_BUF;
        const __half* pBh = sBh + buf * B_BUF;

#pragma unroll
        for (int step = 0; step < 2; step++) {
            int k0 = step * 16;
            unsigned ah[4][4], al[4][4], bh[2][4];
#pragma unroll
            for (int mi = 0; mi < 4; mi++) {
                int m = wm * 64 + mi * 16 + aRow;
                ldsm4(ah[mi], pAh + m * ASTRIDE + k0 + aCol);
                ldsm4(al[mi], pAl + m * ASTRIDE + k0 + aCol);
            }
#pragma unroll
            for (int ng = 0; ng < 2; ng++) {
                int n = wn * 32 + ng * 16 + bCol;
                ldsm4t(bh[ng], pBh + (k0 + bRow) * BSTRIDE + n);
            }
#pragma unroll
            for (int mi = 0; mi < 4; mi++)
#pragma unroll
                for (int ng = 0; ng < 2; ng++)
#pragma unroll
                    for (int hf = 0; hf < 2; hf++) {
                        int nj = ng * 2 + hf;
                        unsigned bhf[2] = {bh[ng][hf * 2], bh[ng][hf * 2 + 1]};
                        mma_f16(acc[mi][nj], ah[mi], bhf);
                        mma_f16(acc[mi][nj], al[mi], bhf);
                    }
        }
        __syncthreads();
        buf ^= 1;
    }

    int r = lane >> 2, cl = lane & 3;
#pragma unroll
    for (int mi = 0; mi < 4; mi++) {
#pragma unroll
        for (int nj = 0; nj < 4; nj++) {
            int row = m0 + wm * 64 + mi * 16 + r;
            int col = n0 + wn * 32 + nj * 8 + cl * 2;
            *(float2*)(out + (size_t)row * ND + col)       = make_float2(acc[mi][nj][0], acc[mi][nj][1]);
            *(float2*)(out + (size_t)(row + 8) * ND + col) = make_float2(acc[mi][nj][2], acc[mi][nj][3]);
        }
    }
}

// ---------------- stage 4b: bias + LayerNorm (in-place over out) ----------------
__global__ void __launch_bounds__(256) k_ln(const float* __restrict__ bc,
                                            const float* __restrict__ gamma,
                                            const float* __restrict__ beta,
                                            float* __restrict__ out) {
    __shared__ float sbf[ND], sg[ND], sbe[ND];
    int tid = threadIdx.x;
#pragma unroll
    for (int q = 0; q < 2; q++) {
        int i = tid + q * 256;
        sbf[i] = bc[i]; sg[i] = gamma[i]; sbe[i] = beta[i];
    }
    __syncthreads();

    int lane = tid & 31;
    int wrp  = tid >> 5;
    int row  = blockIdx.x * 8 + wrp;

    float* rp = out + (size_t)row * ND;
    float v[16];
    float s = 0.f, sq = 0.f;
#pragma unroll
    for (int q = 0; q < 4; q++) {
        int c = lane * 4 + q * 128;
        float4 x = *(const float4*)(rp + c);
        float4 bb = *(const float4*)(sbf + c);
        v[q * 4 + 0] = x.x + bb.x;
        v[q * 4 + 1] = x.y + bb.y;
        v[q * 4 + 2] = x.z + bb.z;
        v[q * 4 + 3] = x.w + bb.w;
#pragma unroll
        for (int j = 0; j < 4; j++) {
            s  += v[q * 4 + j];
            sq += v[q * 4 + j] * v[q * 4 + j];
        }
    }
#pragma unroll
    for (int off = 16; off > 0; off >>= 1) {
        s  += __shfl_xor_sync(0xffffffffu, s, off);
        sq += __shfl_xor_sync(0xffffffffu, sq, off);
    }
    float mu  = s * (1.0f / 512.0f);
    float var = sq * (1.0f / 512.0f) - mu * mu;
    float rstd = rsqrtf(var + 1e-5f);
#pragma unroll
    for (int q = 0; q < 4; q++) {
        int c = lane * 4 + q * 128;
        float4 gg = *(const float4*)(sg + c);
        float4 be = *(const float4*)(sbe + c);
        float4 o;
        o.x = (v[q * 4 + 0] - mu) * rstd * gg.x + be.x;
        o.y = (v[q * 4 + 1] - mu) * rstd * gg.y + be.y;
        o.z = (v[q * 4 + 2] - mu) * rstd * gg.z + be.z;
        o.w = (v[q * 4 + 3] - mu) * rstd * gg.w + be.w;
        *(float4*)(rp + c) = o;
    }
}

// ---------------- launch ----------------
extern "C" void kernel_launch(void* const* d_in, const int* in_sizes, int n_in,
                              void* d_out, int out_size) {
    const float* outp  = (const float*)d_in[0];
    const float* attn  = (const float*)d_in[1];
    const float* oeh   = (const float*)d_in[2];
    const void*  ei    = d_in[3];
    const float* Wg    = (const float*)d_in[6];
    const float* bg    = (const float*)d_in[7];
    const float* Wl    = (const float*)d_in[8];
    const float* bl    = (const float*)d_in[9];
    const float* Wch   = (const float*)d_in[10];
    const float* bch   = (const float*)d_in[11];
    const float* Wc    = (const float*)d_in[12];
    const float* bc    = (const float*)d_in[13];
    const float* gamma = (const float*)d_in[14];
    const float* beta  = (const float*)d_in[15];
    float* out = (float*)d_out;

    int cheb_smem = 3 * NN * TST * 4;
    cudaFuncSetAttribute(k_cheb, cudaFuncAttributeMaxDynamicSharedMemorySize, cheb_smem);
    int gemm_smem = (4 * A_BUF + 2 * B_BUF) * 2;   // bytes (fp16)
    cudaFuncSetAttribute(k_gemm, cudaFuncAttributeMaxDynamicSharedMemorySize, gemm_smem);

    k_detect<<<1, 32>>>((const int*)ei);
    k_prep<<<8784, 256>>>(outp, Wc, Wch);
    k_coeff<<<NG, 256>>>(attn, Wg, bg, Wl, bl);
    k_degk<<<NE / 256, 256>>>(ei);
    k_scan<<<1, 512>>>();
    k_scatter<<<NE / 256, 256>>>(ei);
    k_cheb<<<NG, 512, cheb_smem>>>(oeh, bch);
    dim3 gg2(128, 4);
    k_gemm<<<gg2, 256, gemm_smem>>>(out);
    k_ln<<<NTOT / 8, 256>>>(bc, gamma, beta, out);
}

// round 17
// speedup vs baseline: 2.0633x; 1.0013x over previous
#include <cuda_runtime.h>
#include <cuda_bf16.h>
#include <cuda_fp16.h>

// Problem constants
#define NB   64
#define NN   256
#define NH   8
#define NDH  64
#define ND   512
#define NK   1024       // 2*D concat width
#define NTOT 16384      // B*N
#define NE   262144     // TOTAL*DEG
#define NG   512        // H*B graphs
#define TST  68         // T-buffer row stride (floats)

// mega-kernel block ranges
#define MG_COEFF0 0
#define MG_PREP0  512            // 512 coeff blocks
#define MG_DEGK0  (512 + 8720)   // 8720 prep blocks
#define MG_TOTAL  (512 + 8720 + 1024)

// ---------------- device scratch ----------------
__device__ int            g_is64;
__device__ float          g_coeff[NG * 4];
__device__ float          g_dinv[NTOT];
__device__ int            g_deg[NTOT];
__device__ int            g_off[NTOT + 1];
__device__ int            g_cur[NTOT];
__device__ int2           g_epack[NE];
// fp16 hi/lo A = [outp | cheb_filtered] rows (n,b)-order; W_cat fp16 [K=1024][N=512]
__device__ __half         g_Ahi[(size_t)NTOT * NK];
__device__ __half         g_Alo[(size_t)NTOT * NK];
__device__ __half         g_Bh [(size_t)NK * ND];
// W_cheb in mma-fragment-linear order (fp16)
__device__ uint2          g_Wf[4 * 4 * 8 * 32];

// fp16 hi/lo pack
__device__ __forceinline__ void cvt_hilo_h(float x, float y, unsigned& h, unsigned& l) {
    __half hx = __float2half_rn(x);
    __half hy = __float2half_rn(y);
    h = (unsigned)__half_as_ushort(hx) | ((unsigned)__half_as_ushort(hy) << 16);
    __half lx = __float2half_rn(x - __half2float(hx));
    __half ly = __float2half_rn(y - __half2float(hy));
    l = (unsigned)__half_as_ushort(lx) | ((unsigned)__half_as_ushort(ly) << 16);
}
__device__ __forceinline__ unsigned pack_h2(float x, float y) {
    __half hx = __float2half_rn(x);
    __half hy = __float2half_rn(y);
    return (unsigned)__half_as_ushort(hx) | ((unsigned)__half_as_ushort(hy) << 16);
}

__device__ __forceinline__ void load_edge(const void* ei, int e, int& s, int& d) {
    if (g_is64) {
        const long long* p = (const long long*)ei;
        s = (int)p[e];
        d = (int)p[NE + e];
    } else {
        const int* p = (const int*)ei;
        s = p[e];
        d = p[NE + e];
    }
}

// ---------------- front0: zero counters + dtype detect ----------------
__global__ void k_front0(const int* p) {
    if (blockIdx.x < 64) {
        int i = blockIdx.x * 256 + threadIdx.x;
        g_deg[i] = 0;
        g_cur[i] = 0;
    } else if (threadIdx.x == 0) {
        int ok64 = 1;
        for (int q = 1; q < 64; q += 2)
            if (p[q] != 0) ok64 = 0;
        g_is64 = ok64;
    }
}

// ---------------- mega: coeff || prep || degk (independent block ranges) ----------------
__global__ void __launch_bounds__(256) k_mega(const float* __restrict__ attn,
                                              const float* __restrict__ Wg,
                                              const float* __restrict__ bg,
                                              const float* __restrict__ Wl,
                                              const float* __restrict__ bl,
                                              const float* __restrict__ outp,
                                              const float* __restrict__ Wc,
                                              const float* __restrict__ Wch,
                                              const void* ei) {
    int blk = blockIdx.x;
    int tid = threadIdx.x;

    if (blk < MG_PREP0) {
        // ------- coeff: one block per graph -------
        int g = blk;
        int h = g >> 6;
        int b = g & 63;
        const float* A = attn + ((size_t)b * NH + h) * (NN * NN);
        int j = tid;

        __shared__ float dsm[NN];
        __shared__ float red[4];

        float cs = 0.f;
#pragma unroll 16
        for (int i = 0; i < NN; i++) cs += A[i * NN + j];
        float deg = cs + 1.0f;
        float dv = (deg > 0.f) ? rsqrtf(deg) : 0.f;
        dsm[j] = dv;
        if (j < 4) red[j] = 0.f;
        __syncthreads();

        float t = 0.f;
#pragma unroll 16
        for (int i = 0; i < NN; i++) t += dsm[i] * A[i * NN + j];
        float sj = (t + dv) * dv;

        float w_row[4], v[4];
#pragma unroll
        for (int c = 0; c < 4; c++)
            w_row[c] = Wg[c] + Wg[4 + c] + Wg[8 + c] + Wg[12 + c];
#pragma unroll
        for (int c = 0; c < 4; c++)
            v[c] = tanhf(sj * w_row[c] + bg[c]);

#pragma unroll
        for (int c = 0; c < 4; c++) {
#pragma unroll
            for (int off = 16; off > 0; off >>= 1)
                v[c] += __shfl_xor_sync(0xffffffffu, v[c], off);
        }
        if ((j & 31) == 0) {
#pragma unroll
            for (int c = 0; c < 4; c++) atomicAdd(&red[c], v[c]);
        }
        __syncthreads();

        if (j == 0) {
            float gap[4];
#pragma unroll
            for (int c = 0; c < 4; c++) gap[c] = red[c] * (1.0f / 256.0f);
#pragma unroll
            for (int c2 = 0; c2 < 4; c2++) {
                float cc = bl[c2];
#pragma unroll
                for (int c = 0; c < 4; c++) cc += gap[c] * Wl[c * 4 + c2];
                g_coeff[g * 4 + c2] = cc;
            }
        }
    } else if (blk < MG_DEGK0) {
        // ------- prep -------
        int pb = blk - MG_PREP0;
        if (pb < 8192) {
            int idx = pb * 256 + tid;
            int row = idx >> 7;
            int c4  = (idx & 127) * 4;
            float4 x = *(const float4*)(outp + (size_t)row * ND + c4);
            unsigned h01, l01, h23, l23;
            cvt_hilo_h(x.x, x.y, h01, l01);
            cvt_hilo_h(x.z, x.w, h23, l23);
            size_t o = (size_t)row * NK + c4;
            *(uint2*)(g_Ahi + o) = make_uint2(h01, h23);
            *(uint2*)(g_Alo + o) = make_uint2(l01, l23);
        } else if (pb < 8704) {
            int idx = (pb - 8192) * 256 + tid;
            float4 x = *(const float4*)(Wc + (size_t)idx * 4);
            *(uint2*)(g_Bh + (size_t)idx * 4) = make_uint2(pack_h2(x.x, x.y), pack_h2(x.z, x.w));
        } else {
            int i = (pb - 8704) * 256 + tid;
            int lane = i & 31, nt = (i >> 5) & 7, kt = (i >> 8) & 3, k = i >> 10;
            int tt = lane & 3, gg = lane >> 2;
            int n = nt * 8 + gg;
            unsigned h[2];
#pragma unroll
            for (int reg = 0; reg < 2; reg++) {
                int kr = kt * 16 + 2 * tt + reg * 8;
                h[reg] = pack_h2(Wch[k * 4096 + kr * 64 + n], Wch[k * 4096 + (kr + 1) * 64 + n]);
            }
            g_Wf[i] = make_uint2(h[0], h[1]);
        }
    } else {
        // ------- degk -------
        int e = (blk - MG_DEGK0) * 256 + tid;
        if (e < NE) {
            int s, d;
            load_edge(ei, e, s, d);
            atomicAdd(&g_deg[d], 1);
        }
    }
}

// ---------------- stage 2b/2c: scan + scatter ----------------
__global__ void __launch_bounds__(512) k_scan() {
    __shared__ int sc[512];
    int t = threadIdx.x;
    int base = t * 32;
    int sum = 0;
    for (int i = 0; i < 32; i++) {
        int d = g_deg[base + i];
        g_dinv[base + i] = (d > 0) ? rsqrtf((float)d) : 0.f;
        sum += d;
    }
    sc[t] = sum;
    __syncthreads();
    for (int off = 1; off < 512; off <<= 1) {
        int v = sc[t];
        int u = (t >= off) ? sc[t - off] : 0;
        __syncthreads();
        sc[t] = v + u;
        __syncthreads();
    }
    int run = sc[t] - sum;
    for (int i = 0; i < 32; i++) {
        g_off[base + i] = run;
        run += g_deg[base + i];
    }
    if (t == 511) g_off[NTOT] = sc[511];
}

__global__ void k_scatter(const void* ei) {
    int e = blockIdx.x * blockDim.x + threadIdx.x;
    if (e < NE) {
        int s, d;
        load_edge(ei, e, s, d);
        float nm = -(g_dinv[s] * g_dinv[d]);
        int pos = g_off[d] + atomicAdd(&g_cur[d], 1);
        g_epack[pos] = make_int2(s & (NN - 1), __float_as_int(nm));
    }
}

// ---------------- mma helper ----------------
__device__ __forceinline__ void mma_f16(float* c, const unsigned* a, const unsigned* b) {
    asm volatile(
        "mma.sync.aligned.m16n8k16.row.col.f32.f16.f16.f32 "
        "{%0,%1,%2,%3}, {%4,%5,%6,%7}, {%8,%9}, {%0,%1,%2,%3};"
        : "+f"(c[0]), "+f"(c[1]), "+f"(c[2]), "+f"(c[3])
        : "r"(a[0]), "r"(a[1]), "r"(a[2]), "r"(a[3]), "r"(b[0]), "r"(b[1]));
}

// ---------------- stage 3: Chebyshev prop + tensor-core matmul (2x fp16) ----------------
__global__ void __launch_bounds__(512, 1) k_cheb(const float* __restrict__ oeh,
                                                 const float* __restrict__ bch) {
    extern __shared__ float sm[];
    float* S0 = sm;
    float* S1 = sm + NN * TST;
    float* S2 = sm + 2 * NN * TST;

    int g = blockIdx.x;
    int h = g >> 6;
    int b = g & 63;
    int tid = threadIdx.x;
    int w = tid >> 5;
    int lane = tid & 31;
    int n0 = w * 16;
    int gr = lane >> 2, tt = lane & 3;

    const float* xb = oeh + (size_t)b * 131072 + (size_t)h * 64;
    for (int idx = tid; idx < NN * NDH; idx += 512) {
        int n = idx >> 6, d = idx & 63;
        S0[n * TST + d] = xb[(size_t)n * 512 + d];
    }

    float c[4];
#pragma unroll
    for (int k = 0; k < 4; k++) c[k] = g_coeff[g * 4 + k];

    float accf[8][4];
#pragma unroll
    for (int nt = 0; nt < 8; nt++)
#pragma unroll
        for (int q = 0; q < 4; q++) accf[nt][q] = 0.f;

    __syncthreads();

    auto matmul = [&](const float* T, int k) {
        float ck = c[k];
#pragma unroll
        for (int kt = 0; kt < 4; kt++) {
            int kc = kt * 16 + 2 * tt;
            float2 x0 = *(const float2*)&T[(n0 + gr) * TST + kc];
            float2 x1 = *(const float2*)&T[(n0 + gr + 8) * TST + kc];
            float2 x2 = *(const float2*)&T[(n0 + gr) * TST + kc + 8];
            float2 x3 = *(const float2*)&T[(n0 + gr + 8) * TST + kc + 8];
            unsigned ah[4], al[4];
            cvt_hilo_h(ck * x0.x, ck * x0.y, ah[0], al[0]);
            cvt_hilo_h(ck * x1.x, ck * x1.y, ah[1], al[1]);
            cvt_hilo_h(ck * x2.x, ck * x2.y, ah[2], al[2]);
            cvt_hilo_h(ck * x3.x, ck * x3.y, ah[3], al[3]);
            const uint2* WF = g_Wf + ((k * 4 + kt) * 8) * 32 + lane;
#pragma unroll
            for (int nt = 0; nt < 8; nt++) {
                uint2 bh = WF[nt * 32];
                unsigned bhv[2] = {bh.x, bh.y};
                mma_f16(accf[nt], ah, bhv);
                mma_f16(accf[nt], al, bhv);
            }
        }
    };

    auto prop = [&](const float* Tsrc, const float* Tprev, float* Tdst, bool first) {
        for (int i = 0; i < 16; i++) {
            int n = n0 + i;
            int dn = b * NN + n;
            int eb = g_off[dn], ee = g_off[dn + 1];
            float s0a = 0.f, s1a = 0.f, s0b = 0.f, s1b = 0.f;
            int e = eb;
            for (; e + 1 < ee; e += 2) {
                int2 e0 = g_epack[e];
                int2 e1 = g_epack[e + 1];
                float w0 = __int_as_float(e0.y);
                float w1 = __int_as_float(e1.y);
                float2 t0 = *(const float2*)&Tsrc[e0.x * TST + 2 * lane];
                float2 t1 = *(const float2*)&Tsrc[e1.x * TST + 2 * lane];
                s0a += w0 * t0.x; s1a += w0 * t0.y;
                s0b += w1 * t1.x; s1b += w1 * t1.y;
            }
            if (e < ee) {
                int2 e0 = g_epack[e];
                float w0 = __int_as_float(e0.y);
                float2 t0 = *(const float2*)&Tsrc[e0.x * TST + 2 * lane];
                s0a += w0 * t0.x; s1a += w0 * t0.y;
            }
            float s0 = s0a + s0b, s1 = s1a + s1b;
            int o = n * TST + 2 * lane;
            if (first) {
                *(float2*)&Tdst[o] = make_float2(s0, s1);
            } else {
                float2 pv = *(const float2*)&Tprev[o];
                *(float2*)&Tdst[o] = make_float2(2.f * s0 - pv.x, 2.f * s1 - pv.y);
            }
        }
    };

    matmul(S0, 0);
    prop(S0, nullptr, S1, true);
    matmul(S1, 1);
    __syncthreads();
    prop(S1, S0, S2, false);
    matmul(S2, 2);
    __syncthreads();
    prop(S2, S1, S0, false);
    matmul(S0, 3);

    // epilogue: bias + fp16 hi/lo into A cols 512+
#pragma unroll
    for (int nt = 0; nt < 8; nt++) {
        int o = nt * 8 + tt * 2;
        float b0 = bch[o], b1 = bch[o + 1];
        float c0 = accf[nt][0] + b0, c1 = accf[nt][1] + b1;
        float c2 = accf[nt][2] + b0, c3 = accf[nt][3] + b1;
        unsigned h01, l01, h23, l23;
        cvt_hilo_h(c0, c1, h01, l01);
        cvt_hilo_h(c2, c3, h23, l23);
        int nA = n0 + gr;
        size_t r1 = (size_t)(nA * 64 + b) * NK + 512 + h * 64 + o;
        size_t r2 = (size_t)((nA + 8) * 64 + b) * NK + 512 + h * 64 + o;
        *(unsigned*)(g_Ahi + r1) = h01;
        *(unsigned*)(g_Alo + r1) = l01;
        *(unsigned*)(g_Ahi + r2) = h23;
        *(unsigned*)(g_Alo + r2) = l23;
    }
}

// ---------------- stage 4a: 2x-fp16 tensor-core GEMM ----------------
#define ASTRIDE 40     // 32 + 8 pad (fp16 el)
#define BSTRIDE 136    // 128 + 8 pad
#define A_BUF   (128 * ASTRIDE)
#define B_BUF   (32 * BSTRIDE)

__device__ __forceinline__ void cp16(void* smem_dst, const void* gmem_src) {
    unsigned s = (unsigned)__cvta_generic_to_shared(smem_dst);
    asm volatile("cp.async.cg.shared.global [%0], [%1], 16;" :: "r"(s), "l"(gmem_src));
}
__device__ __forceinline__ void cp_commit() { asm volatile("cp.async.commit_group;"); }
template <int N>
__device__ __forceinline__ void cp_wait() { asm volatile("cp.async.wait_group %0;" :: "n"(N)); }

__device__ __forceinline__ void ldsm4(unsigned* r, const void* p) {
    unsigned s = (unsigned)__cvta_generic_to_shared(p);
    asm volatile("ldmatrix.sync.aligned.m8n8.x4.shared.b16 {%0,%1,%2,%3}, [%4];"
                 : "=r"(r[0]), "=r"(r[1]), "=r"(r[2]), "=r"(r[3]) : "r"(s));
}
__device__ __forceinline__ void ldsm4t(unsigned* r, const void* p) {
    unsigned s = (unsigned)__cvta_generic_to_shared(p);
    asm volatile("ldmatrix.sync.aligned.m8n8.x4.trans.shared.b16 {%0,%1,%2,%3}, [%4];"
                 : "=r"(r[0]), "=r"(r[1]), "=r"(r[2]), "=r"(r[3]) : "r"(s));
}

__global__ void __launch_bounds__(256) k_gemm(float* __restrict__ out) {
    extern __shared__ __half sh[];
    __half* sAh = sh;
    __half* sAl = sh + 2 * A_BUF;
    __half* sBh = sh + 4 * A_BUF;

    int tid  = threadIdx.x;
    int wid  = tid >> 5;
    int lane = tid & 31;
    int wm   = wid >> 2;
    int wn   = wid & 3;
    int m0   = blockIdx.x * 128;
    int n0   = blockIdx.y * 128;

    float acc[4][4][4];
#pragma unroll
    for (int mi = 0; mi < 4; mi++)
#pragma unroll
        for (int nj = 0; nj < 4; nj++)
#pragma unroll
            for (int q = 0; q < 4; q++) acc[mi][nj][q] = 0.f;

    auto load_stage = [&](int kb, int buf) {
#pragma unroll
        for (int q = 0; q < 2; q++) {
            int cc = tid + q * 256;
            int row = cc >> 2, seg = (cc & 3) * 8;
            size_t go = (size_t)(m0 + row) * NK + kb * 32 + seg;
            int so = buf * A_BUF + row * ASTRIDE + seg;
            cp16(sAh + so, g_Ahi + go);
            cp16(sAl + so, g_Alo + go);
        }
#pragma unroll
        for (int q = 0; q < 2; q++) {
            int cc = tid + q * 256;
            int row = cc >> 4, seg = (cc & 15) * 8;
            size_t go = (size_t)(kb * 32 + row) * ND + n0 + seg;
            int so = buf * B_BUF + row * BSTRIDE + seg;
            cp16(sBh + so, g_Bh + go);
        }
    };

    load_stage(0, 0);
    cp_commit();

    int aRow = lane & 15, aCol = (lane >> 4) * 8;
    int bRow = lane & 15, bCol = (lane >> 4) * 8;
    int buf = 0;

    for (int kb = 0; kb < 32; kb++) {
        if (kb + 1 < 32) { load_stage(kb + 1, buf ^ 1); cp_commit(); cp_wait<1>(); }
        else             { cp_wait<0>(); }
        __syncthreads();

        const __half* pAh = sAh + buf * A_BUF;
        const __half* pAl = sAl + buf * A_BUF;
        const __half* pBh = sBh + buf * B_BUF;

#pragma unroll
        for (int step = 0; step < 2; step++) {
            int k0 = step * 16;
            unsigned ah[4][4], al[4][4], bh[2][4];
#pragma unroll
            for (int mi = 0; mi < 4; mi++) {
                int m = wm * 64 + mi * 16 + aRow;
                ldsm4(ah[mi], pAh + m * ASTRIDE + k0 + aCol);
                ldsm4(al[mi], pAl + m * ASTRIDE + k0 + aCol);
            }
#pragma unroll
            for (int ng = 0; ng < 2; ng++) {
                int n = wn * 32 + ng * 16 + bCol;
                ldsm4t(bh[ng], pBh + (k0 + bRow) * BSTRIDE + n);
            }
#pragma unroll
            for (int mi = 0; mi < 4; mi++)
#pragma unroll
                for (int ng = 0; ng < 2; ng++)
#pragma unroll
                    for (int hf = 0; hf < 2; hf++) {
                        int nj = ng * 2 + hf;
                        unsigned bhf[2] = {bh[ng][hf * 2], bh[ng][hf * 2 + 1]};
                        mma_f16(acc[mi][nj], ah[mi], bhf);
                        mma_f16(acc[mi][nj], al[mi], bhf);
                    }
        }
        __syncthreads();
        buf ^= 1;
    }

    int r = lane >> 2, cl = lane & 3;
#pragma unroll
    for (int mi = 0; mi < 4; mi++) {
#pragma unroll
        for (int nj = 0; nj < 4; nj++) {
            int row = m0 + wm * 64 + mi * 16 + r;
            int col = n0 + wn * 32 + nj * 8 + cl * 2;
            *(float2*)(out + (size_t)row * ND + col)       = make_float2(acc[mi][nj][0], acc[mi][nj][1]);
            *(float2*)(out + (size_t)(row + 8) * ND + col) = make_float2(acc[mi][nj][2], acc[mi][nj][3]);
        }
    }
}

// ---------------- stage 4b: bias + LayerNorm (in-place over out) ----------------
__global__ void __launch_bounds__(256) k_ln(const float* __restrict__ bc,
                                            const float* __restrict__ gamma,
                                            const float* __restrict__ beta,
                                            float* __restrict__ out) {
    __shared__ float sbf[ND], sg[ND], sbe[ND];
    int tid = threadIdx.x;
#pragma unroll
    for (int q = 0; q < 2; q++) {
        int i = tid + q * 256;
        sbf[i] = bc[i]; sg[i] = gamma[i]; sbe[i] = beta[i];
    }
    __syncthreads();

    int lane = tid & 31;
    int wrp  = tid >> 5;
    int row  = blockIdx.x * 8 + wrp;

    float* rp = out + (size_t)row * ND;
    float v[16];
    float s = 0.f, sq = 0.f;
#pragma unroll
    for (int q = 0; q < 4; q++) {
        int c = lane * 4 + q * 128;
        float4 x = *(const float4*)(rp + c);
        float4 bb = *(const float4*)(sbf + c);
        v[q * 4 + 0] = x.x + bb.x;
        v[q * 4 + 1] = x.y + bb.y;
        v[q * 4 + 2] = x.z + bb.z;
        v[q * 4 + 3] = x.w + bb.w;
#pragma unroll
        for (int j = 0; j < 4; j++) {
            s  += v[q * 4 + j];
            sq += v[q * 4 + j] * v[q * 4 + j];
        }
    }
#pragma unroll
    for (int off = 16; off > 0; off >>= 1) {
        s  += __shfl_xor_sync(0xffffffffu, s, off);
        sq += __shfl_xor_sync(0xffffffffu, sq, off);
    }
    float mu  = s * (1.0f / 512.0f);
    float var = sq * (1.0f / 512.0f) - mu * mu;
    float rstd = rsqrtf(var + 1e-5f);
#pragma unroll
    for (int q = 0; q < 4; q++) {
        int c = lane * 4 + q * 128;
        float4 gg = *(const float4*)(sg + c);
        float4 be = *(const float4*)(sbe + c);
        float4 o;
        o.x = (v[q * 4 + 0] - mu) * rstd * gg.x + be.x;
        o.y = (v[q * 4 + 1] - mu) * rstd * gg.y + be.y;
        o.z = (v[q * 4 + 2] - mu) * rstd * gg.z + be.z;
        o.w = (v[q * 4 + 3] - mu) * rstd * gg.w + be.w;
        *(float4*)(rp + c) = o;
    }
}

// ---------------- launch ----------------
extern "C" void kernel_launch(void* const* d_in, const int* in_sizes, int n_in,
                              void* d_out, int out_size) {
    const float* outp  = (const float*)d_in[0];
    const float* attn  = (const float*)d_in[1];
    const float* oeh   = (const float*)d_in[2];
    const void*  ei    = d_in[3];
    const float* Wg    = (const float*)d_in[6];
    const float* bg    = (const float*)d_in[7];
    const float* Wl    = (const float*)d_in[8];
    const float* bl    = (const float*)d_in[9];
    const float* Wch   = (const float*)d_in[10];
    const float* bch   = (const float*)d_in[11];
    const float* Wc    = (const float*)d_in[12];
    const float* bc    = (const float*)d_in[13];
    const float* gamma = (const float*)d_in[14];
    const float* beta  = (const float*)d_in[15];
    float* out = (float*)d_out;

    int cheb_smem = 3 * NN * TST * 4;
    cudaFuncSetAttribute(k_cheb, cudaFuncAttributeMaxDynamicSharedMemorySize, cheb_smem);
    int gemm_smem = (4 * A_BUF + 2 * B_BUF) * 2;   // bytes (fp16)
    cudaFuncSetAttribute(k_gemm, cudaFuncAttributeMaxDynamicSharedMemorySize, gemm_smem);

    k_front0<<<65, 256>>>((const int*)ei);
    k_mega<<<MG_TOTAL, 256>>>(attn, Wg, bg, Wl, bl, outp, Wc, Wch, ei);
    k_scan<<<1, 512>>>();
    k_scatter<<<NE / 256, 256>>>(ei);
    k_cheb<<<NG, 512, cheb_smem>>>(oeh, bch);
    dim3 gg2(128, 4);
    k_gemm<<<gg2, 256, gemm_smem>>>(out);
    k_ln<<<NTOT / 8, 256>>>(bc, gamma, beta, out);
}